// round 5
// baseline (speedup 1.0000x reference)
#include <cuda_runtime.h>
#include <cstdint>
#include <cmath>

#define BSZ   32
#define SEQ   128
#define HID   512
#define NGATE 1536
#define VOC   32000
#define NTOK  4096   /* BSZ*SEQ */

// ---------------- device scratch (no allocations allowed) ----------------
__device__ int      g_tok[NTOK];
__device__ float    g_xg[(size_t)NTOK * NGATE];    // [S][B][3H], b_ih folded in
__device__ float    g_hs_tf[(size_t)NTOK * HID];   // tf32-rounded hidden states
__device__ float    g_wout_tf[(size_t)VOC * HID];  // tf32-rounded W_out
__device__ float    g_h[2][BSZ * HID];             // ping-pong hidden state
__device__ unsigned g_arr[128 * 32];               // per-CTA arrival slots (128B apart)
__device__ unsigned g_flag[128 * 32];              // per-CTA release flags (128B apart)

__device__ __forceinline__ unsigned f2tf(float x) {
    unsigned r;
    asm("cvt.rna.tf32.f32 %0, %1;" : "=r"(r) : "f"(x));
    return r;
}
__device__ __forceinline__ uint32_t s2u(const void* p) {
    uint32_t a;
    asm("{ .reg .u64 t; cvta.to.shared.u64 t, %1; cvt.u32.u64 %0, t; }"
        : "=r"(a) : "l"(p));
    return a;
}

// targets may be int32 (JAX x64 disabled) or int64. Detect: int64 tokens
// always have zero high words -> first 8 int64 views all in [0, VOC).
__device__ __forceinline__ bool tok_is64(const void* p) {
    const long long* q = (const long long*)p;
    bool ok = true;
#pragma unroll
    for (int i = 0; i < 8; ++i) {
        long long v = q[i];
        ok = ok && (v >= 0) && (v < VOC);
    }
    return ok;
}
__device__ __forceinline__ int tok_at(const void* p, int idx, bool is64) {
    return is64 ? (int)((const long long*)p)[idx] : ((const int*)p)[idx];
}

__device__ __forceinline__ float fsigm(float x) {
    return __fdividef(1.f, 1.f + __expf(-x));
}
__device__ __forceinline__ float ftanh(float x) {
    float ax = fabsf(x);
    float e  = __expf(-2.f * ax);
    float t  = __fdividef(1.f - e, 1.f + e);
    return copysignf(t, x);
}

__device__ __forceinline__ void mma8(float* c, const uint32_t* a,
                                     uint32_t b0, uint32_t b1) {
    asm volatile(
        "mma.sync.aligned.m16n8k8.row.col.f32.tf32.tf32.f32 "
        "{%0,%1,%2,%3}, {%4,%5,%6,%7}, {%8,%9}, {%0,%1,%2,%3};"
        : "+f"(c[0]), "+f"(c[1]), "+f"(c[2]), "+f"(c[3])
        : "r"(a[0]), "r"(a[1]), "r"(a[2]), "r"(a[3]), "r"(b0), "r"(b1));
}

// ---------------- init: token indices, h0, barrier reset -----------------
__global__ void init_kernel(const void* __restrict__ targets,
                            const int* __restrict__ init_tok,
                            const float* __restrict__ hidden) {
    const bool is64 = tok_is64(targets);
    int t = blockIdx.x * blockDim.x + threadIdx.x;
    int nt = gridDim.x * blockDim.x;
    for (int i = t; i < 128 * 32; i += nt) { g_arr[i] = 0u; g_flag[i] = 0u; }
    if (t < NTOK) {
        int s = t >> 5, b = t & 31;
        g_tok[t] = (s == 0) ? init_tok[0]
                            : tok_at(targets, b * SEQ + (s - 1), is64);
    }
    for (int i = t; i < BSZ * HID; i += nt)
        g_h[0][i] = hidden[i];
}

// ---------------- pre-convert W_out to tf32 (RNA) ------------------------
__global__ void conv_w(const float* __restrict__ W) {
    int t = blockIdx.x * blockDim.x + threadIdx.x;
    int nt = gridDim.x * blockDim.x;
    const int n4 = (VOC * HID) / 4;
    for (int i = t; i < n4; i += nt) {
        float4 v = ((const float4*)W)[i];
        float4 o;
        o.x = __uint_as_float(f2tf(v.x));
        o.y = __uint_as_float(f2tf(v.y));
        o.z = __uint_as_float(f2tf(v.z));
        o.w = __uint_as_float(f2tf(v.w));
        ((float4*)g_wout_tf)[i] = o;
    }
}

// ---------------- x_gates GEMM (embedding gather, mma.sync) --------------
__global__ void __launch_bounds__(256, 2)
gemm_xg(const float* __restrict__ A, const float* __restrict__ Bm,
        const float* __restrict__ bias) {
    __shared__ unsigned As[128 * 36];
    __shared__ unsigned Bs[128 * 36];

    const int tid  = threadIdx.x;
    const int n0   = blockIdx.x * 128;
    const int m0   = blockIdx.y * 128;
    const int lane = tid & 31, warp = tid >> 5;
    const int wm = warp & 1, wn = warp >> 1;
    const int g  = lane >> 2, tg = lane & 3;

    const float* aptr[4];
    const float* bptr[4];
    int soff[4];
#pragma unroll
    for (int i = 0; i < 4; ++i) {
        int idx = tid + i * 256;
        int row = idx >> 3, cv = idx & 7;
        int arow = g_tok[m0 + row];
        aptr[i] = A + (size_t)arow * HID + cv * 4;
        bptr[i] = Bm + (size_t)(n0 + row) * HID + cv * 4;
        soff[i] = row * 36 + cv * 4;
    }

    float c[4][4][4];
#pragma unroll
    for (int a = 0; a < 4; ++a)
#pragma unroll
        for (int b = 0; b < 4; ++b)
#pragma unroll
            for (int k = 0; k < 4; ++k) c[a][b][k] = 0.f;

    for (int kt = 0; kt < 16; ++kt) {
        float4 va[4], vb[4];
#pragma unroll
        for (int i = 0; i < 4; ++i) {
            va[i] = *(const float4*)(aptr[i] + kt * 32);
            vb[i] = *(const float4*)(bptr[i] + kt * 32);
        }
        __syncthreads();
#pragma unroll
        for (int i = 0; i < 4; ++i) {
            As[soff[i] + 0] = f2tf(va[i].x); As[soff[i] + 1] = f2tf(va[i].y);
            As[soff[i] + 2] = f2tf(va[i].z); As[soff[i] + 3] = f2tf(va[i].w);
            Bs[soff[i] + 0] = f2tf(vb[i].x); Bs[soff[i] + 1] = f2tf(vb[i].y);
            Bs[soff[i] + 2] = f2tf(vb[i].z); Bs[soff[i] + 3] = f2tf(vb[i].w);
        }
        __syncthreads();

#pragma unroll
        for (int kk = 0; kk < 4; ++kk) {
            const int kb = kk * 8;
            unsigned afr[4][4], bfr[4][2];
#pragma unroll
            for (int mf = 0; mf < 4; ++mf) {
                int r0 = (wm * 64 + mf * 16 + g) * 36 + kb + tg;
                afr[mf][0] = As[r0];
                afr[mf][1] = As[r0 + 8 * 36];
                afr[mf][2] = As[r0 + 4];
                afr[mf][3] = As[r0 + 8 * 36 + 4];
            }
#pragma unroll
            for (int nf = 0; nf < 4; ++nf) {
                int r0 = (wn * 32 + nf * 8 + g) * 36 + kb + tg;
                bfr[nf][0] = Bs[r0];
                bfr[nf][1] = Bs[r0 + 4];
            }
#pragma unroll
            for (int mf = 0; mf < 4; ++mf)
#pragma unroll
                for (int nf = 0; nf < 4; ++nf)
                    mma8(c[mf][nf], afr[mf], bfr[nf][0], bfr[nf][1]);
        }
    }

#pragma unroll
    for (int mf = 0; mf < 4; ++mf) {
#pragma unroll
        for (int nf = 0; nf < 4; ++nf) {
            int row = m0 + wm * 64 + mf * 16 + g;
            int col = n0 + wn * 32 + nf * 8 + 2 * tg;
            float b0v = bias[col], b1v = bias[col + 1];
            float2 v0 = make_float2(c[mf][nf][0] + b0v, c[mf][nf][1] + b1v);
            float2 v1 = make_float2(c[mf][nf][2] + b0v, c[mf][nf][3] + b1v);
            *(float2*)&g_xg[(size_t)row * NGATE + col]       = v0;
            *(float2*)&g_xg[(size_t)(row + 8) * NGATE + col] = v1;
        }
    }
}

// ---------------- logits GEMM: cp.async 3-stage, 64x64 warp tiles --------
// CTA tile 128(M) x 256(N), K chunks of 16. Inputs pre-rounded to tf32.
// smem row stride 24 words (16 k + 8 pad) -> LDS.64 frag pairs conflict-free.
#define GK    16
#define NCH   32          /* 512 / 16 */
#define AW    (128 * 24)  /* words per A stage */
#define BW    (256 * 24)
#define STW   (AW + BW)   /* 9216 words = 36864 B per stage */
#define SMEM2 (3 * STW * 4)

__global__ void __launch_bounds__(256, 1)
gemm_tc2(const float* __restrict__ bias, float* __restrict__ out) {
    extern __shared__ float smemf[];
    const uint32_t sb = s2u(smemf);
    const int tid  = threadIdx.x;
    const int wid  = tid >> 5, lane = tid & 31;
    const int wm = wid & 1, wn = wid >> 1;         // 2 x 4 warps
    const int g  = lane >> 2, tg = lane & 3;
    const int n0 = blockIdx.x * 256, m0 = blockIdx.y * 128;

    const float* asrc[2]; uint32_t adst[2];
    const float* bsrc[4]; uint32_t bdst[4];
#pragma unroll
    for (int i = 0; i < 2; ++i) {
        int idx = tid + i * 256, r = idx >> 2, c4 = idx & 3;
        asrc[i] = g_hs_tf + (size_t)(m0 + r) * HID + c4 * 4;
        adst[i] = (uint32_t)((r * 24 + c4 * 4) * 4);
    }
#pragma unroll
    for (int i = 0; i < 4; ++i) {
        int idx = tid + i * 256, r = idx >> 2, c4 = idx & 3;
        bsrc[i] = g_wout_tf + (size_t)(n0 + r) * HID + c4 * 4;
        bdst[i] = (uint32_t)((AW * 4) + (r * 24 + c4 * 4) * 4);
    }

    float c[4][8][4];
#pragma unroll
    for (int mf = 0; mf < 4; ++mf)
#pragma unroll
        for (int nf = 0; nf < 8; ++nf)
#pragma unroll
            for (int k = 0; k < 4; ++k) c[mf][nf][k] = 0.f;

#pragma unroll 1
    for (int pc = 0; pc < 2; ++pc) {      // prologue: stages 0,1
        uint32_t sbase = sb + (uint32_t)(pc * STW * 4);
        int kb = pc * GK;
#pragma unroll
        for (int i = 0; i < 2; ++i)
            asm volatile("cp.async.cg.shared.global [%0], [%1], 16;"
                         :: "r"(sbase + adst[i]), "l"(asrc[i] + kb) : "memory");
#pragma unroll
        for (int i = 0; i < 4; ++i)
            asm volatile("cp.async.cg.shared.global [%0], [%1], 16;"
                         :: "r"(sbase + bdst[i]), "l"(bsrc[i] + kb) : "memory");
        asm volatile("cp.async.commit_group;" ::: "memory");
    }

#pragma unroll 1
    for (int ch = 0; ch < NCH; ++ch) {
        asm volatile("cp.async.wait_group 1;" ::: "memory");
        __syncthreads();

        // issue chunk ch+2 into stage (ch+2)%3 (fully read at iter ch-1)
        {
            int nc = ch + 2;
            if (nc < NCH) {
                uint32_t sbase = sb + (uint32_t)((nc % 3) * STW * 4);
                int kb = nc * GK;
#pragma unroll
                for (int i = 0; i < 2; ++i)
                    asm volatile("cp.async.cg.shared.global [%0], [%1], 16;"
                                 :: "r"(sbase + adst[i]), "l"(asrc[i] + kb)
                                 : "memory");
#pragma unroll
                for (int i = 0; i < 4; ++i)
                    asm volatile("cp.async.cg.shared.global [%0], [%1], 16;"
                                 :: "r"(sbase + bdst[i]), "l"(bsrc[i] + kb)
                                 : "memory");
            }
            asm volatile("cp.async.commit_group;" ::: "memory");
        }

        const uint32_t sbase = sb + (uint32_t)((ch % 3) * STW * 4);
#pragma unroll
        for (int k8 = 0; k8 < 2; ++k8) {
            uint32_t a[4][4];
#pragma unroll
            for (int mf = 0; mf < 4; ++mf) {
                int r0 = wm * 64 + mf * 16 + g;
                uint32_t ad0 = sbase + (uint32_t)((r0 * 24 + k8 * 8 + tg * 2) * 4);
                uint32_t ad1 = sbase + (uint32_t)(((r0 + 8) * 24 + k8 * 8 + tg * 2) * 4);
                asm volatile("ld.shared.v2.b32 {%0,%1}, [%2];"
                             : "=r"(a[mf][0]), "=r"(a[mf][2]) : "r"(ad0));
                asm volatile("ld.shared.v2.b32 {%0,%1}, [%2];"
                             : "=r"(a[mf][1]), "=r"(a[mf][3]) : "r"(ad1));
            }
#pragma unroll
            for (int nf = 0; nf < 8; ++nf) {
                int rn = wn * 64 + nf * 8 + g;
                uint32_t bd = sbase +
                    (uint32_t)((AW + rn * 24 + k8 * 8 + tg * 2) * 4);
                uint32_t b0, b1;
                asm volatile("ld.shared.v2.b32 {%0,%1}, [%2];"
                             : "=r"(b0), "=r"(b1) : "r"(bd));
#pragma unroll
                for (int mf = 0; mf < 4; ++mf)
                    mma8(c[mf][nf], a[mf], b0, b1);
            }
        }
    }

    // epilogue: rows -> (s,b) remap, add bias
#pragma unroll
    for (int mf = 0; mf < 4; ++mf) {
        int row = m0 + wm * 64 + mf * 16 + g;
        int s0 = row >> 5, b0i = row & 31;
        int r1 = row + 8;
        int s1 = r1 >> 5, b1i = r1 & 31;
        float* o0 = out + ((size_t)b0i * SEQ + s0) * VOC;
        float* o1 = out + ((size_t)b1i * SEQ + s1) * VOC;
#pragma unroll
        for (int nf = 0; nf < 8; ++nf) {
            int col = n0 + wn * 64 + nf * 8 + 2 * tg;
            float bv0 = bias[col], bv1 = bias[col + 1];
            *(float2*)(o0 + col) = make_float2(c[mf][nf][0] + bv0,
                                               c[mf][nf][1] + bv1);
            *(float2*)(o1 + col) = make_float2(c[mf][nf][2] + bv0,
                                               c[mf][nf][3] + bv1);
        }
    }
}

// ---------------- persistent GRU scan: 128 CTAs ---------------------------
// Arrival: per-CTA release store (no atomic serialization). CTA 0 warp 0
// collects 128 slots, then releases 128 distributed flags.
__global__ void recur_kernel(const float* __restrict__ W_hh,
                             const float* __restrict__ b_hh) {
    extern __shared__ float sm[];
    float* h_sm    = sm;                  // 16384 floats
    float* w_sm    = sm + BSZ * HID;      // 12*512 floats
    float* bias_sm = w_sm + 12 * HID;     // 12 floats

    const int tid = threadIdx.x;
    const int j0  = blockIdx.x * 4;

    for (int i = tid; i < 12 * HID; i += 256) {
        int r = i >> 9, k = i & 511;
        int jl = r / 3, gg = r % 3;
        w_sm[i] = W_hh[(size_t)(gg * HID + j0 + jl) * HID + k];
    }
    if (tid < 12) {
        int jl = tid / 3, gg = tid % 3;
        bias_sm[tid] = b_hh[gg * HID + j0 + jl];
    }

    const int ks = tid & 15;
    const int bq = (tid >> 4) & 3;
    const int jl = tid >> 6;
    const int j  = j0 + jl;
    const float* wr = w_sm + (jl * 3 + 0) * HID;
    const float* wz = w_sm + (jl * 3 + 1) * HID;
    const float* wn = w_sm + (jl * 3 + 2) * HID;
    __syncthreads();

    for (int s = 0; s < SEQ; ++s) {
        float xr[8], xz[8], xn[8];
        if (ks == 0) {
#pragma unroll
            for (int bi = 0; bi < 8; ++bi) {
                int b = bq * 8 + bi;
                const float* xg = g_xg + (size_t)(s * BSZ + b) * NGATE;
                xr[bi] = __ldg(xg + j);
                xz[bi] = __ldg(xg + HID + j);
                xn[bi] = __ldg(xg + 2 * HID + j);
            }
        }

        {
            const float4* src = (const float4*)g_h[s & 1];
            float4* dst = (float4*)h_sm;
            for (int i = tid; i < (BSZ * HID) / 4; i += 256) dst[i] = src[i];
        }
        __syncthreads();

        float ar[8], az[8], an[8];
#pragma unroll
        for (int bi = 0; bi < 8; ++bi) { ar[bi] = az[bi] = an[bi] = 0.f; }
#pragma unroll
        for (int i = 0; i < 8; ++i) {
            int k = ks * 4 + i * 64;
            float4 r4 = *(const float4*)(wr + k);
            float4 z4 = *(const float4*)(wz + k);
            float4 n4 = *(const float4*)(wn + k);
#pragma unroll
            for (int bi = 0; bi < 8; ++bi) {
                int b = bq * 8 + bi;
                float4 h4 = *(const float4*)(h_sm + b * HID + k);
                ar[bi] += h4.x * r4.x + h4.y * r4.y + h4.z * r4.z + h4.w * r4.w;
                az[bi] += h4.x * z4.x + h4.y * z4.y + h4.z * z4.z + h4.w * z4.w;
                an[bi] += h4.x * n4.x + h4.y * n4.y + h4.z * n4.z + h4.w * n4.w;
            }
        }
#pragma unroll
        for (int off = 8; off > 0; off >>= 1) {
#pragma unroll
            for (int bi = 0; bi < 8; ++bi) {
                ar[bi] += __shfl_xor_sync(0xffffffffu, ar[bi], off);
                az[bi] += __shfl_xor_sync(0xffffffffu, az[bi], off);
                an[bi] += __shfl_xor_sync(0xffffffffu, an[bi], off);
            }
        }
        if (ks == 0) {
            float br = bias_sm[jl * 3 + 0];
            float bz = bias_sm[jl * 3 + 1];
            float bn = bias_sm[jl * 3 + 2];
#pragma unroll
            for (int bi = 0; bi < 8; ++bi) {
                int b = bq * 8 + bi;
                float rr = fsigm(xr[bi] + ar[bi] + br);
                float zz = fsigm(xz[bi] + az[bi] + bz);
                float nn = ftanh(xn[bi] + rr * (an[bi] + bn));
                float hold = h_sm[b * HID + j];
                float hnew = (1.f - zz) * nn + zz * hold;
                g_h[(s + 1) & 1][b * HID + j] = hnew;
                g_hs_tf[(size_t)(s * BSZ + b) * HID + j] =
                    __uint_as_float(f2tf(hnew));
            }
        }
        if (s == SEQ - 1) break;

        // ---- grid barrier: store-arrive + collector + distributed release
        __syncthreads();
        const unsigned sv = (unsigned)(s + 1);
        if (tid == 0) {
            asm volatile("st.release.gpu.global.u32 [%0], %1;"
                         :: "l"(&g_arr[blockIdx.x * 32]), "r"(sv) : "memory");
        }
        if (blockIdx.x == 0) {
            if (tid < 32) {
                for (;;) {
                    unsigned ok = 1;
#pragma unroll
                    for (int i = 0; i < 4; ++i) {
                        unsigned v;
                        asm volatile("ld.acquire.gpu.global.u32 %0, [%1];"
                                     : "=r"(v)
                                     : "l"(&g_arr[(tid * 4 + i) * 32])
                                     : "memory");
                        ok &= (v >= sv) ? 1u : 0u;
                    }
                    if (__all_sync(0xffffffffu, ok)) break;
                }
#pragma unroll
                for (int i = 0; i < 4; ++i)
                    asm volatile("st.release.gpu.global.u32 [%0], %1;"
                                 :: "l"(&g_flag[(tid * 4 + i) * 32]), "r"(sv)
                                 : "memory");
            }
        } else if (tid == 0) {
            unsigned v;
            do {
                asm volatile("ld.acquire.gpu.global.u32 %0, [%1];"
                             : "=r"(v) : "l"(&g_flag[blockIdx.x * 32])
                             : "memory");
            } while (v < sv);
        }
        __syncthreads();
    }
}

// ---------------- launch ----------------
extern "C" void kernel_launch(void* const* d_in, const int* in_sizes, int n_in,
                              void* d_out, int out_size) {
    const float* hidden    = (const float*)d_in[0];
    const void*  targets   = (const void*)d_in[1];
    const float* embedding = (const float*)d_in[2];
    const float* W_ih      = (const float*)d_in[3];
    const float* W_hh      = (const float*)d_in[4];
    const float* b_ih      = (const float*)d_in[5];
    const float* b_hh      = (const float*)d_in[6];
    const float* W_out     = (const float*)d_in[7];
    const float* b_out     = (const float*)d_in[8];
    const int*   init_tok  = (const int*)d_in[9];
    float*       out       = (float*)d_out;

    cudaFuncSetAttribute(recur_kernel,
                         cudaFuncAttributeMaxDynamicSharedMemorySize, 92160);
    cudaFuncSetAttribute(gemm_tc2,
                         cudaFuncAttributeMaxDynamicSharedMemorySize, SMEM2);

    init_kernel<<<16, 256>>>(targets, init_tok, hidden);

    // x_gates: [4096 x 1536 x 512], A gathered from embedding
    gemm_xg<<<dim3(NGATE / 128, NTOK / 128), 256>>>(embedding, W_ih, b_ih);

    // pre-round W_out to tf32 (RNA)
    conv_w<<<256, 256>>>(W_out);

    // sequential GRU scan (persistent, 128 co-resident CTAs)
    recur_kernel<<<128, 256, 92160>>>(W_hh, b_hh);

    // logits: [4096 x 32000 x 512], tiles 125 x 32
    gemm_tc2<<<dim3(VOC / 256, NTOK / 128), 256, SMEM2>>>(b_out, out);
}

// round 6
// speedup vs baseline: 1.1435x; 1.1435x over previous
#include <cuda_runtime.h>
#include <cstdint>
#include <cmath>

#define BSZ   32
#define SEQ   128
#define HID   512
#define NGATE 1536
#define VOC   32000
#define NTOK  4096   /* BSZ*SEQ */

// ---------------- device scratch (no allocations allowed) ----------------
__device__ int      g_tok[NTOK];
__device__ float    g_xg[(size_t)NTOK * NGATE];    // [S][B][3H], b_ih folded in
__device__ float    g_hs_tf[(size_t)NTOK * HID];   // tf32-rounded hidden states
__device__ float    g_wout_tf[(size_t)VOC * HID];  // tf32-rounded W_out
__device__ float    g_h[2][BSZ * HID];             // ping-pong hidden state
__device__ unsigned g_arr[128 * 32];               // per-CTA arrival slots (128B apart)

__device__ __forceinline__ unsigned f2tf(float x) {
    unsigned r;
    asm("cvt.rna.tf32.f32 %0, %1;" : "=r"(r) : "f"(x));
    return r;
}
__device__ __forceinline__ uint32_t s2u(const void* p) {
    uint32_t a;
    asm("{ .reg .u64 t; cvta.to.shared.u64 t, %1; cvt.u32.u64 %0, t; }"
        : "=r"(a) : "l"(p));
    return a;
}

// targets may be int32 (JAX x64 disabled) or int64. Detect: int64 tokens
// always have zero high words -> first 8 int64 views all in [0, VOC).
__device__ __forceinline__ bool tok_is64(const void* p) {
    const long long* q = (const long long*)p;
    bool ok = true;
#pragma unroll
    for (int i = 0; i < 8; ++i) {
        long long v = q[i];
        ok = ok && (v >= 0) && (v < VOC);
    }
    return ok;
}
__device__ __forceinline__ int tok_at(const void* p, int idx, bool is64) {
    return is64 ? (int)((const long long*)p)[idx] : ((const int*)p)[idx];
}

__device__ __forceinline__ float fsigm(float x) {
    return __fdividef(1.f, 1.f + __expf(-x));
}
__device__ __forceinline__ float ftanh(float x) {
    float ax = fabsf(x);
    float e  = __expf(-2.f * ax);
    float t  = __fdividef(1.f - e, 1.f + e);
    return copysignf(t, x);
}

__device__ __forceinline__ void mma8(float* c, const uint32_t* a,
                                     uint32_t b0, uint32_t b1) {
    asm volatile(
        "mma.sync.aligned.m16n8k8.row.col.f32.tf32.tf32.f32 "
        "{%0,%1,%2,%3}, {%4,%5,%6,%7}, {%8,%9}, {%0,%1,%2,%3};"
        : "+f"(c[0]), "+f"(c[1]), "+f"(c[2]), "+f"(c[3])
        : "r"(a[0]), "r"(a[1]), "r"(a[2]), "r"(a[3]), "r"(b0), "r"(b1));
}

// ---------------- init: token indices, h0, barrier reset -----------------
__global__ void init_kernel(const void* __restrict__ targets,
                            const int* __restrict__ init_tok,
                            const float* __restrict__ hidden) {
    const bool is64 = tok_is64(targets);
    int t = blockIdx.x * blockDim.x + threadIdx.x;
    int nt = gridDim.x * blockDim.x;
    for (int i = t; i < 128 * 32; i += nt) g_arr[i] = 0u;
    if (t < NTOK) {
        int s = t >> 5, b = t & 31;
        g_tok[t] = (s == 0) ? init_tok[0]
                            : tok_at(targets, b * SEQ + (s - 1), is64);
    }
    for (int i = t; i < BSZ * HID; i += nt)
        g_h[0][i] = hidden[i];
}

// ---------------- pre-convert W_out to tf32 (RNA) ------------------------
__global__ void conv_w(const float* __restrict__ W) {
    int t = blockIdx.x * blockDim.x + threadIdx.x;
    int nt = gridDim.x * blockDim.x;
    const int n4 = (VOC * HID) / 4;
    for (int i = t; i < n4; i += nt) {
        float4 v = ((const float4*)W)[i];
        float4 o;
        o.x = __uint_as_float(f2tf(v.x));
        o.y = __uint_as_float(f2tf(v.y));
        o.z = __uint_as_float(f2tf(v.z));
        o.w = __uint_as_float(f2tf(v.w));
        ((float4*)g_wout_tf)[i] = o;
    }
}

// ---------------- x_gates GEMM (embedding gather, mma.sync) --------------
__global__ void __launch_bounds__(256, 2)
gemm_xg(const float* __restrict__ A, const float* __restrict__ Bm,
        const float* __restrict__ bias) {
    __shared__ unsigned As[128 * 36];
    __shared__ unsigned Bs[128 * 36];

    const int tid  = threadIdx.x;
    const int n0   = blockIdx.x * 128;
    const int m0   = blockIdx.y * 128;
    const int lane = tid & 31, warp = tid >> 5;
    const int wm = warp & 1, wn = warp >> 1;
    const int g  = lane >> 2, tg = lane & 3;

    const float* aptr[4];
    const float* bptr[4];
    int soff[4];
#pragma unroll
    for (int i = 0; i < 4; ++i) {
        int idx = tid + i * 256;
        int row = idx >> 3, cv = idx & 7;
        int arow = g_tok[m0 + row];
        aptr[i] = A + (size_t)arow * HID + cv * 4;
        bptr[i] = Bm + (size_t)(n0 + row) * HID + cv * 4;
        soff[i] = row * 36 + cv * 4;
    }

    float c[4][4][4];
#pragma unroll
    for (int a = 0; a < 4; ++a)
#pragma unroll
        for (int b = 0; b < 4; ++b)
#pragma unroll
            for (int k = 0; k < 4; ++k) c[a][b][k] = 0.f;

    for (int kt = 0; kt < 16; ++kt) {
        float4 va[4], vb[4];
#pragma unroll
        for (int i = 0; i < 4; ++i) {
            va[i] = *(const float4*)(aptr[i] + kt * 32);
            vb[i] = *(const float4*)(bptr[i] + kt * 32);
        }
        __syncthreads();
#pragma unroll
        for (int i = 0; i < 4; ++i) {
            As[soff[i] + 0] = f2tf(va[i].x); As[soff[i] + 1] = f2tf(va[i].y);
            As[soff[i] + 2] = f2tf(va[i].z); As[soff[i] + 3] = f2tf(va[i].w);
            Bs[soff[i] + 0] = f2tf(vb[i].x); Bs[soff[i] + 1] = f2tf(vb[i].y);
            Bs[soff[i] + 2] = f2tf(vb[i].z); Bs[soff[i] + 3] = f2tf(vb[i].w);
        }
        __syncthreads();

#pragma unroll
        for (int kk = 0; kk < 4; ++kk) {
            const int kb = kk * 8;
            unsigned afr[4][4], bfr[4][2];
#pragma unroll
            for (int mf = 0; mf < 4; ++mf) {
                int r0 = (wm * 64 + mf * 16 + g) * 36 + kb + tg;
                afr[mf][0] = As[r0];
                afr[mf][1] = As[r0 + 8 * 36];
                afr[mf][2] = As[r0 + 4];
                afr[mf][3] = As[r0 + 8 * 36 + 4];
            }
#pragma unroll
            for (int nf = 0; nf < 4; ++nf) {
                int r0 = (wn * 32 + nf * 8 + g) * 36 + kb + tg;
                bfr[nf][0] = Bs[r0];
                bfr[nf][1] = Bs[r0 + 4];
            }
#pragma unroll
            for (int mf = 0; mf < 4; ++mf)
#pragma unroll
                for (int nf = 0; nf < 4; ++nf)
                    mma8(c[mf][nf], afr[mf], bfr[nf][0], bfr[nf][1]);
        }
    }

#pragma unroll
    for (int mf = 0; mf < 4; ++mf) {
#pragma unroll
        for (int nf = 0; nf < 4; ++nf) {
            int row = m0 + wm * 64 + mf * 16 + g;
            int col = n0 + wn * 32 + nf * 8 + 2 * tg;
            float b0v = bias[col], b1v = bias[col + 1];
            float2 v0 = make_float2(c[mf][nf][0] + b0v, c[mf][nf][1] + b1v);
            float2 v1 = make_float2(c[mf][nf][2] + b0v, c[mf][nf][3] + b1v);
            *(float2*)&g_xg[(size_t)row * NGATE + col]       = v0;
            *(float2*)&g_xg[(size_t)(row + 8) * NGATE + col] = v1;
        }
    }
}

// ---------------- logits GEMM: cp.async 3-stage, 64x32 warp tiles --------
// CTA tile 128 x 128, 8 warps, occ 2 (16 warps/SM like the proven config).
// Inputs pre-rounded to tf32. Row stride 24 words; k-relabel trick makes
// every fragment pair one LDS.64, conflict-free per half-warp phase.
#define GK    16
#define NCH   32            /* 512 / 16 */
#define AW3   (128 * 24)    /* words per A stage */
#define STW3  (2 * AW3)     /* 6144 words = 24576 B per stage */
#define SMEM3 (3 * STW3 * 4)

__global__ void __launch_bounds__(256, 2)
gemm3(const float* __restrict__ bias, float* __restrict__ out) {
    extern __shared__ float smemf[];
    const uint32_t sb = s2u(smemf);
    const int tid  = threadIdx.x;
    const int wid  = tid >> 5, lane = tid & 31;
    const int wm = wid & 1, wn = wid >> 1;         // 2 x 4 warps
    const int g  = lane >> 2, tg = lane & 3;
    const int n0 = blockIdx.x * 128, m0 = blockIdx.y * 128;

    const float* asrc[2]; uint32_t adst[2];
    const float* bsrc[2]; uint32_t bdst[2];
#pragma unroll
    for (int i = 0; i < 2; ++i) {
        int idx = tid + i * 256, r = idx >> 2, c4 = idx & 3;
        asrc[i] = g_hs_tf + (size_t)(m0 + r) * HID + c4 * 4;
        adst[i] = (uint32_t)((r * 24 + c4 * 4) * 4);
        bsrc[i] = g_wout_tf + (size_t)(n0 + r) * HID + c4 * 4;
        bdst[i] = (uint32_t)((AW3 + r * 24 + c4 * 4) * 4);
    }

    float c[4][4][4];
#pragma unroll
    for (int mf = 0; mf < 4; ++mf)
#pragma unroll
        for (int nf = 0; nf < 4; ++nf)
#pragma unroll
            for (int k = 0; k < 4; ++k) c[mf][nf][k] = 0.f;

#pragma unroll
    for (int pc = 0; pc < 2; ++pc) {      // prologue: stages 0,1
        uint32_t sbase = sb + (uint32_t)(pc * STW3 * 4);
        int kb = pc * GK;
#pragma unroll
        for (int i = 0; i < 2; ++i) {
            asm volatile("cp.async.cg.shared.global [%0], [%1], 16;"
                         :: "r"(sbase + adst[i]), "l"(asrc[i] + kb) : "memory");
            asm volatile("cp.async.cg.shared.global [%0], [%1], 16;"
                         :: "r"(sbase + bdst[i]), "l"(bsrc[i] + kb) : "memory");
        }
        asm volatile("cp.async.commit_group;" ::: "memory");
    }

#pragma unroll 1
    for (int ch = 0; ch < NCH; ++ch) {
        asm volatile("cp.async.wait_group 1;" ::: "memory");
        __syncthreads();

        {   // issue chunk ch+2 into stage (ch+2)%3 (fully read at iter ch-1)
            int nc = ch + 2;
            if (nc < NCH) {
                uint32_t sbase = sb + (uint32_t)((nc % 3) * STW3 * 4);
                int kb = nc * GK;
#pragma unroll
                for (int i = 0; i < 2; ++i) {
                    asm volatile("cp.async.cg.shared.global [%0], [%1], 16;"
                                 :: "r"(sbase + adst[i]), "l"(asrc[i] + kb)
                                 : "memory");
                    asm volatile("cp.async.cg.shared.global [%0], [%1], 16;"
                                 :: "r"(sbase + bdst[i]), "l"(bsrc[i] + kb)
                                 : "memory");
                }
            }
            asm volatile("cp.async.commit_group;" ::: "memory");
        }

        const uint32_t sbase = sb + (uint32_t)((ch % 3) * STW3 * 4);
#pragma unroll
        for (int k8 = 0; k8 < 2; ++k8) {
            uint32_t a[4][4];
#pragma unroll
            for (int mf = 0; mf < 4; ++mf) {
                int r0 = wm * 64 + mf * 16 + g;
                uint32_t ad0 = sbase + (uint32_t)((r0 * 24 + k8 * 8 + tg * 2) * 4);
                uint32_t ad1 = sbase +
                    (uint32_t)(((r0 + 8) * 24 + k8 * 8 + tg * 2) * 4);
                asm volatile("ld.shared.v2.b32 {%0,%1}, [%2];"
                             : "=r"(a[mf][0]), "=r"(a[mf][2]) : "r"(ad0));
                asm volatile("ld.shared.v2.b32 {%0,%1}, [%2];"
                             : "=r"(a[mf][1]), "=r"(a[mf][3]) : "r"(ad1));
            }
#pragma unroll
            for (int nf = 0; nf < 4; ++nf) {
                int rn = wn * 32 + nf * 8 + g;
                uint32_t bd = sbase +
                    (uint32_t)((AW3 + rn * 24 + k8 * 8 + tg * 2) * 4);
                uint32_t b0, b1;
                asm volatile("ld.shared.v2.b32 {%0,%1}, [%2];"
                             : "=r"(b0), "=r"(b1) : "r"(bd));
#pragma unroll
                for (int mf = 0; mf < 4; ++mf)
                    mma8(c[mf][nf], a[mf], b0, b1);
            }
        }
    }

    // epilogue: rows -> (s,b) remap, add bias
#pragma unroll
    for (int mf = 0; mf < 4; ++mf) {
        int row = m0 + wm * 64 + mf * 16 + g;
        int s0 = row >> 5, b0i = row & 31;
        int r1 = row + 8;
        int s1 = r1 >> 5, b1i = r1 & 31;
        float* o0 = out + ((size_t)b0i * SEQ + s0) * VOC;
        float* o1 = out + ((size_t)b1i * SEQ + s1) * VOC;
#pragma unroll
        for (int nf = 0; nf < 4; ++nf) {
            int col = n0 + wn * 32 + nf * 8 + 2 * tg;
            float bv0 = bias[col], bv1 = bias[col + 1];
            *(float2*)(o0 + col) = make_float2(c[mf][nf][0] + bv0,
                                               c[mf][nf][1] + bv1);
            *(float2*)(o1 + col) = make_float2(c[mf][nf][2] + bv0,
                                               c[mf][nf][3] + bv1);
        }
    }
}

// ---------------- persistent GRU scan: 128 CTAs ---------------------------
// Barrier: parallel release-store arrival; every CTA's warp 0 polls all 128
// slots (4/lane, independent L2 lines). No atomic serialization, no hop.
__global__ void recur_kernel(const float* __restrict__ W_hh,
                             const float* __restrict__ b_hh) {
    extern __shared__ float sm[];
    float* h_sm    = sm;                  // 16384 floats
    float* w_sm    = sm + BSZ * HID;      // 12*512 floats
    float* bias_sm = w_sm + 12 * HID;     // 12 floats

    const int tid = threadIdx.x;
    const int j0  = blockIdx.x * 4;

    for (int i = tid; i < 12 * HID; i += 256) {
        int r = i >> 9, k = i & 511;
        int jl = r / 3, gg = r % 3;
        w_sm[i] = W_hh[(size_t)(gg * HID + j0 + jl) * HID + k];
    }
    if (tid < 12) {
        int jl = tid / 3, gg = tid % 3;
        bias_sm[tid] = b_hh[gg * HID + j0 + jl];
    }

    const int ks = tid & 15;
    const int bq = (tid >> 4) & 3;
    const int jl = tid >> 6;
    const int j  = j0 + jl;
    const float* wr = w_sm + (jl * 3 + 0) * HID;
    const float* wz = w_sm + (jl * 3 + 1) * HID;
    const float* wn = w_sm + (jl * 3 + 2) * HID;
    __syncthreads();

    for (int s = 0; s < SEQ; ++s) {
        float xr[8], xz[8], xn[8];
        if (ks == 0) {
#pragma unroll
            for (int bi = 0; bi < 8; ++bi) {
                int b = bq * 8 + bi;
                const float* xg = g_xg + (size_t)(s * BSZ + b) * NGATE;
                xr[bi] = __ldg(xg + j);
                xz[bi] = __ldg(xg + HID + j);
                xn[bi] = __ldg(xg + 2 * HID + j);
            }
        }

        {
            const float4* src = (const float4*)g_h[s & 1];
            float4* dst = (float4*)h_sm;
            for (int i = tid; i < (BSZ * HID) / 4; i += 256) dst[i] = src[i];
        }
        __syncthreads();

        float ar[8], az[8], an[8];
#pragma unroll
        for (int bi = 0; bi < 8; ++bi) { ar[bi] = az[bi] = an[bi] = 0.f; }
#pragma unroll
        for (int i = 0; i < 8; ++i) {
            int k = ks * 4 + i * 64;
            float4 r4 = *(const float4*)(wr + k);
            float4 z4 = *(const float4*)(wz + k);
            float4 n4 = *(const float4*)(wn + k);
#pragma unroll
            for (int bi = 0; bi < 8; ++bi) {
                int b = bq * 8 + bi;
                float4 h4 = *(const float4*)(h_sm + b * HID + k);
                ar[bi] += h4.x * r4.x + h4.y * r4.y + h4.z * r4.z + h4.w * r4.w;
                az[bi] += h4.x * z4.x + h4.y * z4.y + h4.z * z4.z + h4.w * z4.w;
                an[bi] += h4.x * n4.x + h4.y * n4.y + h4.z * n4.z + h4.w * n4.w;
            }
        }
#pragma unroll
        for (int off = 8; off > 0; off >>= 1) {
#pragma unroll
            for (int bi = 0; bi < 8; ++bi) {
                ar[bi] += __shfl_xor_sync(0xffffffffu, ar[bi], off);
                az[bi] += __shfl_xor_sync(0xffffffffu, az[bi], off);
                an[bi] += __shfl_xor_sync(0xffffffffu, an[bi], off);
            }
        }
        if (ks == 0) {
            float br = bias_sm[jl * 3 + 0];
            float bz = bias_sm[jl * 3 + 1];
            float bn = bias_sm[jl * 3 + 2];
#pragma unroll
            for (int bi = 0; bi < 8; ++bi) {
                int b = bq * 8 + bi;
                float rr = fsigm(xr[bi] + ar[bi] + br);
                float zz = fsigm(xz[bi] + az[bi] + bz);
                float nn = ftanh(xn[bi] + rr * (an[bi] + bn));
                float hold = h_sm[b * HID + j];
                float hnew = (1.f - zz) * nn + zz * hold;
                g_h[(s + 1) & 1][b * HID + j] = hnew;
                g_hs_tf[(size_t)(s * BSZ + b) * HID + j] =
                    __uint_as_float(f2tf(hnew));
            }
        }
        if (s == SEQ - 1) break;

        // ---- grid barrier: store-arrive + all-poll-all ----
        __syncthreads();
        const unsigned sv = (unsigned)(s + 1);
        if (tid == 0) {
            asm volatile("st.release.gpu.global.u32 [%0], %1;"
                         :: "l"(&g_arr[blockIdx.x * 32]), "r"(sv) : "memory");
        }
        if (tid < 32) {
            for (;;) {
                unsigned ok = 1;
#pragma unroll
                for (int i = 0; i < 4; ++i) {
                    unsigned v;
                    asm volatile("ld.acquire.gpu.global.u32 %0, [%1];"
                                 : "=r"(v)
                                 : "l"(&g_arr[(tid * 4 + i) * 32])
                                 : "memory");
                    ok &= (v >= sv) ? 1u : 0u;
                }
                if (__all_sync(0xffffffffu, ok)) break;
            }
        }
        __syncthreads();
    }
}

// ---------------- launch ----------------
extern "C" void kernel_launch(void* const* d_in, const int* in_sizes, int n_in,
                              void* d_out, int out_size) {
    const float* hidden    = (const float*)d_in[0];
    const void*  targets   = (const void*)d_in[1];
    const float* embedding = (const float*)d_in[2];
    const float* W_ih      = (const float*)d_in[3];
    const float* W_hh      = (const float*)d_in[4];
    const float* b_ih      = (const float*)d_in[5];
    const float* b_hh      = (const float*)d_in[6];
    const float* W_out     = (const float*)d_in[7];
    const float* b_out     = (const float*)d_in[8];
    const int*   init_tok  = (const int*)d_in[9];
    float*       out       = (float*)d_out;

    cudaFuncSetAttribute(recur_kernel,
                         cudaFuncAttributeMaxDynamicSharedMemorySize, 92160);
    cudaFuncSetAttribute(gemm3,
                         cudaFuncAttributeMaxDynamicSharedMemorySize, SMEM3);

    init_kernel<<<16, 256>>>(targets, init_tok, hidden);

    // x_gates: [4096 x 1536 x 512], A gathered from embedding
    gemm_xg<<<dim3(NGATE / 128, NTOK / 128), 256>>>(embedding, W_ih, b_ih);

    // pre-round W_out to tf32 (RNA)
    conv_w<<<256, 256>>>(W_out);

    // sequential GRU scan (persistent, 128 co-resident CTAs)
    recur_kernel<<<128, 256, 92160>>>(W_hh, b_hh);

    // logits: [4096 x 32000 x 512]
    gemm3<<<dim3(VOC / 128, NTOK / 128), 256, SMEM3>>>(b_out, out);
}

// round 7
// speedup vs baseline: 1.5658x; 1.3693x over previous
#include <cuda_runtime.h>
#include <cstdint>
#include <cmath>

#define BSZ   32
#define SEQ   128
#define HID   512
#define NGATE 1536
#define VOC   32000
#define NTOK  4096   /* BSZ*SEQ */

// ---------------- device scratch (no allocations allowed) ----------------
__device__ int      g_tok[NTOK];
__device__ float    g_xg[(size_t)NTOK * NGATE];    // [S][B][3H], b_ih folded in
__device__ float    g_hs_tf[(size_t)NTOK * HID];   // tf32-rounded hidden states
__device__ float    g_wout_tf[(size_t)VOC * HID];  // tf32-rounded W_out
__device__ float    g_h[2][BSZ * HID];             // ping-pong hidden state
__device__ unsigned g_arr[128 * 32];               // per-CTA arrival slots (128B apart)

__device__ __forceinline__ unsigned f2tf(float x) {
    unsigned r;
    asm("cvt.rna.tf32.f32 %0, %1;" : "=r"(r) : "f"(x));
    return r;
}
__device__ __forceinline__ uint32_t s2u(const void* p) {
    uint32_t a;
    asm("{ .reg .u64 t; cvta.to.shared.u64 t, %1; cvt.u32.u64 %0, t; }"
        : "=r"(a) : "l"(p));
    return a;
}

// targets may be int32 (JAX x64 disabled) or int64. Detect: int64 tokens
// always have zero high words -> first 8 int64 views all in [0, VOC).
__device__ __forceinline__ bool tok_is64(const void* p) {
    const long long* q = (const long long*)p;
    bool ok = true;
#pragma unroll
    for (int i = 0; i < 8; ++i) {
        long long v = q[i];
        ok = ok && (v >= 0) && (v < VOC);
    }
    return ok;
}
__device__ __forceinline__ int tok_at(const void* p, int idx, bool is64) {
    return is64 ? (int)((const long long*)p)[idx] : ((const int*)p)[idx];
}

__device__ __forceinline__ float fsigm(float x) {
    return __fdividef(1.f, 1.f + __expf(-x));
}
__device__ __forceinline__ float ftanh(float x) {
    float ax = fabsf(x);
    float e  = __expf(-2.f * ax);
    float t  = __fdividef(1.f - e, 1.f + e);
    return copysignf(t, x);
}

__device__ __forceinline__ void mma8(float* c, const uint32_t* a,
                                     uint32_t b0, uint32_t b1) {
    asm volatile(
        "mma.sync.aligned.m16n8k8.row.col.f32.tf32.tf32.f32 "
        "{%0,%1,%2,%3}, {%4,%5,%6,%7}, {%8,%9}, {%0,%1,%2,%3};"
        : "+f"(c[0]), "+f"(c[1]), "+f"(c[2]), "+f"(c[3])
        : "r"(a[0]), "r"(a[1]), "r"(a[2]), "r"(a[3]), "r"(b0), "r"(b1));
}

// ---------------- init: token indices, h0, barrier reset -----------------
__global__ void init_kernel(const void* __restrict__ targets,
                            const int* __restrict__ init_tok,
                            const float* __restrict__ hidden) {
    const bool is64 = tok_is64(targets);
    int t = blockIdx.x * blockDim.x + threadIdx.x;
    int nt = gridDim.x * blockDim.x;
    for (int i = t; i < 128 * 32; i += nt) g_arr[i] = 0u;
    if (t < NTOK) {
        int s = t >> 5, b = t & 31;
        g_tok[t] = (s == 0) ? init_tok[0]
                            : tok_at(targets, b * SEQ + (s - 1), is64);
    }
    for (int i = t; i < BSZ * HID; i += nt)
        g_h[0][i] = hidden[i];
}

// ---------------- pre-convert W_out to tf32 (RNA) ------------------------
__global__ void conv_w(const float* __restrict__ W) {
    int t = blockIdx.x * blockDim.x + threadIdx.x;
    int nt = gridDim.x * blockDim.x;
    const int n4 = (VOC * HID) / 4;
    for (int i = t; i < n4; i += nt) {
        float4 v = ((const float4*)W)[i];
        float4 o;
        o.x = __uint_as_float(f2tf(v.x));
        o.y = __uint_as_float(f2tf(v.y));
        o.z = __uint_as_float(f2tf(v.z));
        o.w = __uint_as_float(f2tf(v.w));
        ((float4*)g_wout_tf)[i] = o;
    }
}

// ---------------- x_gates GEMM (embedding gather, mma.sync) --------------
__global__ void __launch_bounds__(256, 2)
gemm_xg(const float* __restrict__ A, const float* __restrict__ Bm,
        const float* __restrict__ bias) {
    __shared__ unsigned As[128 * 36];
    __shared__ unsigned Bs[128 * 36];

    const int tid  = threadIdx.x;
    const int n0   = blockIdx.x * 128;
    const int m0   = blockIdx.y * 128;
    const int lane = tid & 31, warp = tid >> 5;
    const int wm = warp & 1, wn = warp >> 1;
    const int g  = lane >> 2, tg = lane & 3;

    const float* aptr[4];
    const float* bptr[4];
    int soff[4];
#pragma unroll
    for (int i = 0; i < 4; ++i) {
        int idx = tid + i * 256;
        int row = idx >> 3, cv = idx & 7;
        int arow = g_tok[m0 + row];
        aptr[i] = A + (size_t)arow * HID + cv * 4;
        bptr[i] = Bm + (size_t)(n0 + row) * HID + cv * 4;
        soff[i] = row * 36 + cv * 4;
    }

    float c[4][4][4];
#pragma unroll
    for (int a = 0; a < 4; ++a)
#pragma unroll
        for (int b = 0; b < 4; ++b)
#pragma unroll
            for (int k = 0; k < 4; ++k) c[a][b][k] = 0.f;

    for (int kt = 0; kt < 16; ++kt) {
        float4 va[4], vb[4];
#pragma unroll
        for (int i = 0; i < 4; ++i) {
            va[i] = *(const float4*)(aptr[i] + kt * 32);
            vb[i] = *(const float4*)(bptr[i] + kt * 32);
        }
        __syncthreads();
#pragma unroll
        for (int i = 0; i < 4; ++i) {
            As[soff[i] + 0] = f2tf(va[i].x); As[soff[i] + 1] = f2tf(va[i].y);
            As[soff[i] + 2] = f2tf(va[i].z); As[soff[i] + 3] = f2tf(va[i].w);
            Bs[soff[i] + 0] = f2tf(vb[i].x); Bs[soff[i] + 1] = f2tf(vb[i].y);
            Bs[soff[i] + 2] = f2tf(vb[i].z); Bs[soff[i] + 3] = f2tf(vb[i].w);
        }
        __syncthreads();

#pragma unroll
        for (int kk = 0; kk < 4; ++kk) {
            const int kb = kk * 8;
            unsigned afr[4][4], bfr[4][2];
#pragma unroll
            for (int mf = 0; mf < 4; ++mf) {
                int r0 = (wm * 64 + mf * 16 + g) * 36 + kb + tg;
                afr[mf][0] = As[r0];
                afr[mf][1] = As[r0 + 8 * 36];
                afr[mf][2] = As[r0 + 4];
                afr[mf][3] = As[r0 + 8 * 36 + 4];
            }
#pragma unroll
            for (int nf = 0; nf < 4; ++nf) {
                int r0 = (wn * 32 + nf * 8 + g) * 36 + kb + tg;
                bfr[nf][0] = Bs[r0];
                bfr[nf][1] = Bs[r0 + 4];
            }
#pragma unroll
            for (int mf = 0; mf < 4; ++mf)
#pragma unroll
                for (int nf = 0; nf < 4; ++nf)
                    mma8(c[mf][nf], afr[mf], bfr[nf][0], bfr[nf][1]);
        }
    }

#pragma unroll
    for (int mf = 0; mf < 4; ++mf) {
#pragma unroll
        for (int nf = 0; nf < 4; ++nf) {
            int row = m0 + wm * 64 + mf * 16 + g;
            int col = n0 + wn * 32 + nf * 8 + 2 * tg;
            float b0v = bias[col], b1v = bias[col + 1];
            float2 v0 = make_float2(c[mf][nf][0] + b0v, c[mf][nf][1] + b1v);
            float2 v1 = make_float2(c[mf][nf][2] + b0v, c[mf][nf][3] + b1v);
            *(float2*)&g_xg[(size_t)row * NGATE + col]       = v0;
            *(float2*)&g_xg[(size_t)(row + 8) * NGATE + col] = v1;
        }
    }
}

// ---------------- logits GEMM: cp.async 3-stage, PDL-overlapped ----------
// CTA tile 128 x 128, 8 warps, occ 2. Inputs pre-rounded to tf32.
// M-tile y consumes scan steps 4y..4y+3 -> poll g_arr >= 4y+4 first.
#define GK    16
#define NCH   32            /* 512 / 16 */
#define AW3   (128 * 24)    /* words per A stage */
#define STW3  (2 * AW3)     /* 6144 words = 24576 B per stage */
#define SMEM3 (3 * STW3 * 4)

__global__ void __launch_bounds__(256, 2)
gemm3(const float* __restrict__ bias, float* __restrict__ out) {
    // ---- PDL gate: wait until the scan has produced this tile's rows ----
    {
        const unsigned need = (unsigned)(blockIdx.y * 4 + 4);
        if (threadIdx.x < 32) {
            for (;;) {
                unsigned ok = 1;
#pragma unroll
                for (int i = 0; i < 4; ++i) {
                    unsigned v;
                    asm volatile("ld.acquire.gpu.global.u32 %0, [%1];"
                                 : "=r"(v)
                                 : "l"(&g_arr[(threadIdx.x * 4 + i) * 32])
                                 : "memory");
                    ok &= (v >= need) ? 1u : 0u;
                }
                if (__all_sync(0xffffffffu, ok)) break;
                __nanosleep(256);
            }
        }
        __syncthreads();
    }

    extern __shared__ float smemf[];
    const uint32_t sb = s2u(smemf);
    const int tid  = threadIdx.x;
    const int wid  = tid >> 5, lane = tid & 31;
    const int wm = wid & 1, wn = wid >> 1;         // 2 x 4 warps
    const int g  = lane >> 2, tg = lane & 3;
    const int n0 = blockIdx.x * 128, m0 = blockIdx.y * 128;

    const float* asrc[2]; uint32_t adst[2];
    const float* bsrc[2]; uint32_t bdst[2];
#pragma unroll
    for (int i = 0; i < 2; ++i) {
        int idx = tid + i * 256, r = idx >> 2, c4 = idx & 3;
        asrc[i] = g_hs_tf + (size_t)(m0 + r) * HID + c4 * 4;
        adst[i] = (uint32_t)((r * 24 + c4 * 4) * 4);
        bsrc[i] = g_wout_tf + (size_t)(n0 + r) * HID + c4 * 4;
        bdst[i] = (uint32_t)((AW3 + r * 24 + c4 * 4) * 4);
    }

    float c[4][4][4];
#pragma unroll
    for (int mf = 0; mf < 4; ++mf)
#pragma unroll
        for (int nf = 0; nf < 4; ++nf)
#pragma unroll
            for (int k = 0; k < 4; ++k) c[mf][nf][k] = 0.f;

#pragma unroll
    for (int pc = 0; pc < 2; ++pc) {      // prologue: stages 0,1
        uint32_t sbase = sb + (uint32_t)(pc * STW3 * 4);
        int kb = pc * GK;
#pragma unroll
        for (int i = 0; i < 2; ++i) {
            asm volatile("cp.async.cg.shared.global [%0], [%1], 16;"
                         :: "r"(sbase + adst[i]), "l"(asrc[i] + kb) : "memory");
            asm volatile("cp.async.cg.shared.global [%0], [%1], 16;"
                         :: "r"(sbase + bdst[i]), "l"(bsrc[i] + kb) : "memory");
        }
        asm volatile("cp.async.commit_group;" ::: "memory");
    }

#pragma unroll 1
    for (int ch = 0; ch < NCH; ++ch) {
        asm volatile("cp.async.wait_group 1;" ::: "memory");
        __syncthreads();

        {   // issue chunk ch+2 into stage (ch+2)%3 (fully read at iter ch-1)
            int nc = ch + 2;
            if (nc < NCH) {
                uint32_t sbase = sb + (uint32_t)((nc % 3) * STW3 * 4);
                int kb = nc * GK;
#pragma unroll
                for (int i = 0; i < 2; ++i) {
                    asm volatile("cp.async.cg.shared.global [%0], [%1], 16;"
                                 :: "r"(sbase + adst[i]), "l"(asrc[i] + kb)
                                 : "memory");
                    asm volatile("cp.async.cg.shared.global [%0], [%1], 16;"
                                 :: "r"(sbase + bdst[i]), "l"(bsrc[i] + kb)
                                 : "memory");
                }
            }
            asm volatile("cp.async.commit_group;" ::: "memory");
        }

        const uint32_t sbase = sb + (uint32_t)((ch % 3) * STW3 * 4);
#pragma unroll
        for (int k8 = 0; k8 < 2; ++k8) {
            uint32_t a[4][4];
#pragma unroll
            for (int mf = 0; mf < 4; ++mf) {
                int r0 = wm * 64 + mf * 16 + g;
                uint32_t ad0 = sbase + (uint32_t)((r0 * 24 + k8 * 8 + tg * 2) * 4);
                uint32_t ad1 = sbase +
                    (uint32_t)(((r0 + 8) * 24 + k8 * 8 + tg * 2) * 4);
                asm volatile("ld.shared.v2.b32 {%0,%1}, [%2];"
                             : "=r"(a[mf][0]), "=r"(a[mf][2]) : "r"(ad0));
                asm volatile("ld.shared.v2.b32 {%0,%1}, [%2];"
                             : "=r"(a[mf][1]), "=r"(a[mf][3]) : "r"(ad1));
            }
#pragma unroll
            for (int nf = 0; nf < 4; ++nf) {
                int rn = wn * 32 + nf * 8 + g;
                uint32_t bd = sbase +
                    (uint32_t)((AW3 + rn * 24 + k8 * 8 + tg * 2) * 4);
                uint32_t b0, b1;
                asm volatile("ld.shared.v2.b32 {%0,%1}, [%2];"
                             : "=r"(b0), "=r"(b1) : "r"(bd));
#pragma unroll
                for (int mf = 0; mf < 4; ++mf)
                    mma8(c[mf][nf], a[mf], b0, b1);
            }
        }
    }

    // epilogue: rows -> (s,b) remap, add bias
#pragma unroll
    for (int mf = 0; mf < 4; ++mf) {
        int row = m0 + wm * 64 + mf * 16 + g;
        int s0 = row >> 5, b0i = row & 31;
        int r1 = row + 8;
        int s1 = r1 >> 5, b1i = r1 & 31;
        float* o0 = out + ((size_t)b0i * SEQ + s0) * VOC;
        float* o1 = out + ((size_t)b1i * SEQ + s1) * VOC;
#pragma unroll
        for (int nf = 0; nf < 4; ++nf) {
            int col = n0 + wn * 32 + nf * 8 + 2 * tg;
            float bv0 = bias[col], bv1 = bias[col + 1];
            *(float2*)(o0 + col) = make_float2(c[mf][nf][0] + bv0,
                                               c[mf][nf][1] + bv1);
            *(float2*)(o1 + col) = make_float2(c[mf][nf][2] + bv0,
                                               c[mf][nf][3] + bv1);
        }
    }
}

// ---------------- persistent GRU scan: 128 CTAs (PDL primary) ------------
__global__ void recur_kernel(const float* __restrict__ W_hh,
                             const float* __restrict__ b_hh) {
    // allow the dependent logits GEMM to start launching now
    asm volatile("griddepcontrol.launch_dependents;" ::: "memory");

    extern __shared__ float sm[];
    float* h_sm    = sm;                  // 16384 floats
    float* w_sm    = sm + BSZ * HID;      // 12*512 floats
    float* bias_sm = w_sm + 12 * HID;     // 12 floats

    const int tid = threadIdx.x;
    const int j0  = blockIdx.x * 4;

    for (int i = tid; i < 12 * HID; i += 256) {
        int r = i >> 9, k = i & 511;
        int jl = r / 3, gg = r % 3;
        w_sm[i] = W_hh[(size_t)(gg * HID + j0 + jl) * HID + k];
    }
    if (tid < 12) {
        int jl = tid / 3, gg = tid % 3;
        bias_sm[tid] = b_hh[gg * HID + j0 + jl];
    }

    const int ks = tid & 15;
    const int bq = (tid >> 4) & 3;
    const int jl = tid >> 6;
    const int j  = j0 + jl;
    const float* wr = w_sm + (jl * 3 + 0) * HID;
    const float* wz = w_sm + (jl * 3 + 1) * HID;
    const float* wn = w_sm + (jl * 3 + 2) * HID;
    __syncthreads();

    for (int s = 0; s < SEQ; ++s) {
        float xr[8], xz[8], xn[8];
        if (ks == 0) {
#pragma unroll
            for (int bi = 0; bi < 8; ++bi) {
                int b = bq * 8 + bi;
                const float* xg = g_xg + (size_t)(s * BSZ + b) * NGATE;
                xr[bi] = __ldg(xg + j);
                xz[bi] = __ldg(xg + HID + j);
                xn[bi] = __ldg(xg + 2 * HID + j);
            }
        }

        {
            const float4* src = (const float4*)g_h[s & 1];
            float4* dst = (float4*)h_sm;
            for (int i = tid; i < (BSZ * HID) / 4; i += 256) dst[i] = src[i];
        }
        __syncthreads();

        float ar[8], az[8], an[8];
#pragma unroll
        for (int bi = 0; bi < 8; ++bi) { ar[bi] = az[bi] = an[bi] = 0.f; }
#pragma unroll
        for (int i = 0; i < 8; ++i) {
            int k = ks * 4 + i * 64;
            float4 r4 = *(const float4*)(wr + k);
            float4 z4 = *(const float4*)(wz + k);
            float4 n4 = *(const float4*)(wn + k);
#pragma unroll
            for (int bi = 0; bi < 8; ++bi) {
                int b = bq * 8 + bi;
                float4 h4 = *(const float4*)(h_sm + b * HID + k);
                ar[bi] += h4.x * r4.x + h4.y * r4.y + h4.z * r4.z + h4.w * r4.w;
                az[bi] += h4.x * z4.x + h4.y * z4.y + h4.z * z4.z + h4.w * z4.w;
                an[bi] += h4.x * n4.x + h4.y * n4.y + h4.z * n4.z + h4.w * n4.w;
            }
        }
#pragma unroll
        for (int off = 8; off > 0; off >>= 1) {
#pragma unroll
            for (int bi = 0; bi < 8; ++bi) {
                ar[bi] += __shfl_xor_sync(0xffffffffu, ar[bi], off);
                az[bi] += __shfl_xor_sync(0xffffffffu, az[bi], off);
                an[bi] += __shfl_xor_sync(0xffffffffu, an[bi], off);
            }
        }
        if (ks == 0) {
            float br = bias_sm[jl * 3 + 0];
            float bz = bias_sm[jl * 3 + 1];
            float bn = bias_sm[jl * 3 + 2];
#pragma unroll
            for (int bi = 0; bi < 8; ++bi) {
                int b = bq * 8 + bi;
                float rr = fsigm(xr[bi] + ar[bi] + br);
                float zz = fsigm(xz[bi] + az[bi] + bz);
                float nn = ftanh(xn[bi] + rr * (an[bi] + bn));
                float hold = h_sm[b * HID + j];
                float hnew = (1.f - zz) * nn + zz * hold;
                g_h[(s + 1) & 1][b * HID + j] = hnew;
                g_hs_tf[(size_t)(s * BSZ + b) * HID + j] =
                    __uint_as_float(f2tf(hnew));
            }
        }
        if (s == SEQ - 1) break;

        // ---- grid barrier: store-arrive + all-poll-all ----
        __syncthreads();
        const unsigned sv = (unsigned)(s + 1);
        if (tid == 0) {
            asm volatile("st.release.gpu.global.u32 [%0], %1;"
                         :: "l"(&g_arr[blockIdx.x * 32]), "r"(sv) : "memory");
        }
        if (tid < 32) {
            for (;;) {
                unsigned ok = 1;
#pragma unroll
                for (int i = 0; i < 4; ++i) {
                    unsigned v;
                    asm volatile("ld.acquire.gpu.global.u32 %0, [%1];"
                                 : "=r"(v)
                                 : "l"(&g_arr[(tid * 4 + i) * 32])
                                 : "memory");
                    ok &= (v >= sv) ? 1u : 0u;
                }
                if (__all_sync(0xffffffffu, ok)) break;
            }
        }
        __syncthreads();
    }

    // final arrival: publish step 128 (releases last 4 M-tiles to gemm3)
    __syncthreads();
    if (tid == 0) {
        asm volatile("st.release.gpu.global.u32 [%0], %1;"
                     :: "l"(&g_arr[blockIdx.x * 32]), "r"((unsigned)SEQ)
                     : "memory");
    }
}

// ---------------- launch ----------------
extern "C" void kernel_launch(void* const* d_in, const int* in_sizes, int n_in,
                              void* d_out, int out_size) {
    const float* hidden    = (const float*)d_in[0];
    const void*  targets   = (const void*)d_in[1];
    const float* embedding = (const float*)d_in[2];
    const float* W_ih      = (const float*)d_in[3];
    const float* W_hh      = (const float*)d_in[4];
    const float* b_ih      = (const float*)d_in[5];
    const float* b_hh      = (const float*)d_in[6];
    const float* W_out     = (const float*)d_in[7];
    const float* b_out     = (const float*)d_in[8];
    const int*   init_tok  = (const int*)d_in[9];
    float*       out       = (float*)d_out;

    cudaFuncSetAttribute(recur_kernel,
                         cudaFuncAttributeMaxDynamicSharedMemorySize, 92160);
    cudaFuncSetAttribute(gemm3,
                         cudaFuncAttributeMaxDynamicSharedMemorySize, SMEM3);

    init_kernel<<<16, 256>>>(targets, init_tok, hidden);

    // x_gates: [4096 x 1536 x 512], A gathered from embedding
    gemm_xg<<<dim3(NGATE / 128, NTOK / 128), 256>>>(embedding, W_ih, b_ih);

    // pre-round W_out to tf32 (RNA)
    conv_w<<<256, 256>>>(W_out);

    // sequential GRU scan (persistent, 128 co-resident CTAs)
    recur_kernel<<<128, 256, 92160>>>(W_hh, b_hh);

    // logits GEMM, PDL-overlapped with the scan; data-gated via g_arr polls
    {
        cudaLaunchConfig_t cfg = {};
        cfg.gridDim  = dim3(VOC / 128, NTOK / 128);
        cfg.blockDim = dim3(256);
        cfg.dynamicSmemBytes = SMEM3;
        cudaLaunchAttribute attr[1];
        attr[0].id = cudaLaunchAttributeProgrammaticStreamSerialization;
        attr[0].val.programmaticStreamSerializationAllowed = 1;
        cfg.attrs = attr;
        cfg.numAttrs = 1;
        cudaLaunchKernelEx(&cfg, gemm3, (const float*)b_out, out);
    }
}

// round 8
// speedup vs baseline: 1.8858x; 1.2043x over previous
#include <cuda_runtime.h>
#include <cuda_fp16.h>
#include <cstdint>
#include <cmath>

#define BSZ   32
#define SEQ   128
#define HID   512
#define NGATE 1536
#define VOC   32000
#define NTOK  4096   /* BSZ*SEQ */

// ---------------- device scratch (no allocations allowed) ----------------
__device__ int      g_tok[NTOK];
__device__ float    g_xg[(size_t)NTOK * NGATE];    // [S][B][3H], b_ih folded in
__device__ __half   g_hs_h[(size_t)NTOK * HID];    // fp16 hidden states
__device__ __half   g_wout_h[(size_t)VOC * HID];   // fp16 W_out
__device__ float    g_h[2][BSZ * HID];             // ping-pong hidden state
__device__ unsigned g_arr[128 * 32];               // per-CTA arrival slots (128B apart)

__device__ __forceinline__ unsigned f2tf(float x) {
    unsigned r;
    asm("cvt.rna.tf32.f32 %0, %1;" : "=r"(r) : "f"(x));
    return r;
}
__device__ __forceinline__ uint32_t s2u(const void* p) {
    uint32_t a;
    asm("{ .reg .u64 t; cvta.to.shared.u64 t, %1; cvt.u32.u64 %0, t; }"
        : "=r"(a) : "l"(p));
    return a;
}

// targets may be int32 (JAX x64 disabled) or int64. Detect: int64 tokens
// always have zero high words -> first 8 int64 views all in [0, VOC).
__device__ __forceinline__ bool tok_is64(const void* p) {
    const long long* q = (const long long*)p;
    bool ok = true;
#pragma unroll
    for (int i = 0; i < 8; ++i) {
        long long v = q[i];
        ok = ok && (v >= 0) && (v < VOC);
    }
    return ok;
}
__device__ __forceinline__ int tok_at(const void* p, int idx, bool is64) {
    return is64 ? (int)((const long long*)p)[idx] : ((const int*)p)[idx];
}

__device__ __forceinline__ float fsigm(float x) {
    return __fdividef(1.f, 1.f + __expf(-x));
}
__device__ __forceinline__ float ftanh(float x) {
    float ax = fabsf(x);
    float e  = __expf(-2.f * ax);
    float t  = __fdividef(1.f - e, 1.f + e);
    return copysignf(t, x);
}

__device__ __forceinline__ void mma8(float* c, const uint32_t* a,
                                     uint32_t b0, uint32_t b1) {
    asm volatile(
        "mma.sync.aligned.m16n8k8.row.col.f32.tf32.tf32.f32 "
        "{%0,%1,%2,%3}, {%4,%5,%6,%7}, {%8,%9}, {%0,%1,%2,%3};"
        : "+f"(c[0]), "+f"(c[1]), "+f"(c[2]), "+f"(c[3])
        : "r"(a[0]), "r"(a[1]), "r"(a[2]), "r"(a[3]), "r"(b0), "r"(b1));
}
__device__ __forceinline__ void mma16h(float* c, uint32_t a0, uint32_t a1,
                                       uint32_t a2, uint32_t a3,
                                       uint32_t b0, uint32_t b1) {
    asm volatile(
        "mma.sync.aligned.m16n8k16.row.col.f32.f16.f16.f32 "
        "{%0,%1,%2,%3}, {%4,%5,%6,%7}, {%8,%9}, {%0,%1,%2,%3};"
        : "+f"(c[0]), "+f"(c[1]), "+f"(c[2]), "+f"(c[3])
        : "r"(a0), "r"(a1), "r"(a2), "r"(a3), "r"(b0), "r"(b1));
}

// ---------------- init: token indices, h0, barrier reset -----------------
__global__ void init_kernel(const void* __restrict__ targets,
                            const int* __restrict__ init_tok,
                            const float* __restrict__ hidden) {
    const bool is64 = tok_is64(targets);
    int t = blockIdx.x * blockDim.x + threadIdx.x;
    int nt = gridDim.x * blockDim.x;
    for (int i = t; i < 128 * 32; i += nt) g_arr[i] = 0u;
    if (t < NTOK) {
        int s = t >> 5, b = t & 31;
        g_tok[t] = (s == 0) ? init_tok[0]
                            : tok_at(targets, b * SEQ + (s - 1), is64);
    }
    for (int i = t; i < BSZ * HID; i += nt)
        g_h[0][i] = hidden[i];
}

// ---------------- pre-convert W_out to fp16 (RN) -------------------------
__global__ void conv_w(const float* __restrict__ W) {
    int t = blockIdx.x * blockDim.x + threadIdx.x;
    int nt = gridDim.x * blockDim.x;
    const int n4 = (VOC * HID) / 4;
    for (int i = t; i < n4; i += nt) {
        float4 v = ((const float4*)W)[i];
        __half2 h01 = __floats2half2_rn(v.x, v.y);
        __half2 h23 = __floats2half2_rn(v.z, v.w);
        *(__half2*)(g_wout_h + (size_t)i * 4)     = h01;
        *(__half2*)(g_wout_h + (size_t)i * 4 + 2) = h23;
    }
}

// ---------------- x_gates GEMM (embedding gather, tf32 mma.sync) ---------
__global__ void __launch_bounds__(256, 2)
gemm_xg(const float* __restrict__ A, const float* __restrict__ Bm,
        const float* __restrict__ bias) {
    __shared__ unsigned As[128 * 36];
    __shared__ unsigned Bs[128 * 36];

    const int tid  = threadIdx.x;
    const int n0   = blockIdx.x * 128;
    const int m0   = blockIdx.y * 128;
    const int lane = tid & 31, warp = tid >> 5;
    const int wm = warp & 1, wn = warp >> 1;
    const int g  = lane >> 2, tg = lane & 3;

    const float* aptr[4];
    const float* bptr[4];
    int soff[4];
#pragma unroll
    for (int i = 0; i < 4; ++i) {
        int idx = tid + i * 256;
        int row = idx >> 3, cv = idx & 7;
        int arow = g_tok[m0 + row];
        aptr[i] = A + (size_t)arow * HID + cv * 4;
        bptr[i] = Bm + (size_t)(n0 + row) * HID + cv * 4;
        soff[i] = row * 36 + cv * 4;
    }

    float c[4][4][4];
#pragma unroll
    for (int a = 0; a < 4; ++a)
#pragma unroll
        for (int b = 0; b < 4; ++b)
#pragma unroll
            for (int k = 0; k < 4; ++k) c[a][b][k] = 0.f;

    for (int kt = 0; kt < 16; ++kt) {
        float4 va[4], vb[4];
#pragma unroll
        for (int i = 0; i < 4; ++i) {
            va[i] = *(const float4*)(aptr[i] + kt * 32);
            vb[i] = *(const float4*)(bptr[i] + kt * 32);
        }
        __syncthreads();
#pragma unroll
        for (int i = 0; i < 4; ++i) {
            As[soff[i] + 0] = f2tf(va[i].x); As[soff[i] + 1] = f2tf(va[i].y);
            As[soff[i] + 2] = f2tf(va[i].z); As[soff[i] + 3] = f2tf(va[i].w);
            Bs[soff[i] + 0] = f2tf(vb[i].x); Bs[soff[i] + 1] = f2tf(vb[i].y);
            Bs[soff[i] + 2] = f2tf(vb[i].z); Bs[soff[i] + 3] = f2tf(vb[i].w);
        }
        __syncthreads();

#pragma unroll
        for (int kk = 0; kk < 4; ++kk) {
            const int kb = kk * 8;
            unsigned afr[4][4], bfr[4][2];
#pragma unroll
            for (int mf = 0; mf < 4; ++mf) {
                int r0 = (wm * 64 + mf * 16 + g) * 36 + kb + tg;
                afr[mf][0] = As[r0];
                afr[mf][1] = As[r0 + 8 * 36];
                afr[mf][2] = As[r0 + 4];
                afr[mf][3] = As[r0 + 8 * 36 + 4];
            }
#pragma unroll
            for (int nf = 0; nf < 4; ++nf) {
                int r0 = (wn * 32 + nf * 8 + g) * 36 + kb + tg;
                bfr[nf][0] = Bs[r0];
                bfr[nf][1] = Bs[r0 + 4];
            }
#pragma unroll
            for (int mf = 0; mf < 4; ++mf)
#pragma unroll
                for (int nf = 0; nf < 4; ++nf)
                    mma8(c[mf][nf], afr[mf], bfr[nf][0], bfr[nf][1]);
        }
    }

#pragma unroll
    for (int mf = 0; mf < 4; ++mf) {
#pragma unroll
        for (int nf = 0; nf < 4; ++nf) {
            int row = m0 + wm * 64 + mf * 16 + g;
            int col = n0 + wn * 32 + nf * 8 + 2 * tg;
            float b0v = bias[col], b1v = bias[col + 1];
            float2 v0 = make_float2(c[mf][nf][0] + b0v, c[mf][nf][1] + b1v);
            float2 v1 = make_float2(c[mf][nf][2] + b0v, c[mf][nf][3] + b1v);
            *(float2*)&g_xg[(size_t)row * NGATE + col]       = v0;
            *(float2*)&g_xg[(size_t)(row + 8) * NGATE + col] = v1;
        }
    }
}

// ---------------- logits GEMM: fp16 m16n8k16, cp.async 3-stage, PDL ------
// CTA 128x128, warp tile 64x32. K chunks of 32 halves (64B rows).
// Row stride 48 halves (96B = 24 words): fragment LDS.64 conflict-free.
// k-relabel: mma k-slot pairs (lo|hi) <- physical halves 4tg..4tg+3 for
// both A and B (sum over k is order-independent).
#define GKH   32            /* halves per chunk */
#define NCHH  16            /* 512 / 32 */
#define RSB   96            /* bytes per row in smem */
#define AWB   (128 * RSB)   /* 12288 B per A stage */
#define STWB  (2 * AWB)     /* 24576 B per stage */
#define SMEMH (3 * STWB)    /* 73728 B */

__global__ void __launch_bounds__(256, 2)
gemm3(const float* __restrict__ bias, float* __restrict__ out) {
    // ---- PDL gate: wait until the scan has produced this tile's rows ----
    {
        const unsigned need = (unsigned)(blockIdx.y * 4 + 4);
        if (threadIdx.x < 32) {
            for (;;) {
                unsigned ok = 1;
#pragma unroll
                for (int i = 0; i < 4; ++i) {
                    unsigned v;
                    asm volatile("ld.acquire.gpu.global.u32 %0, [%1];"
                                 : "=r"(v)
                                 : "l"(&g_arr[(threadIdx.x * 4 + i) * 32])
                                 : "memory");
                    ok &= (v >= need) ? 1u : 0u;
                }
                if (__all_sync(0xffffffffu, ok)) break;
                __nanosleep(256);
            }
        }
        __syncthreads();
    }

    extern __shared__ char smemc[];
    const uint32_t sb = s2u(smemc);
    const int tid  = threadIdx.x;
    const int wid  = tid >> 5, lane = tid & 31;
    const int wm = wid & 1, wn = wid >> 1;         // 2 x 4 warps
    const int g  = lane >> 2, tg = lane & 3;
    const int n0 = blockIdx.x * 128, m0 = blockIdx.y * 128;

    // cp.async slots: 512 x 16B per operand per chunk -> 2 each per thread
    const __half* asrc[2]; uint32_t adst[2];
    const __half* bsrc[2]; uint32_t bdst[2];
#pragma unroll
    for (int i = 0; i < 2; ++i) {
        int idx = tid + i * 256, r = idx >> 2, c4 = idx & 3;
        asrc[i] = g_hs_h + (size_t)(m0 + r) * HID + c4 * 8;
        adst[i] = (uint32_t)(r * RSB + c4 * 16);
        bsrc[i] = g_wout_h + (size_t)(n0 + r) * HID + c4 * 8;
        bdst[i] = (uint32_t)(AWB + r * RSB + c4 * 16);
    }

    float c[4][4][4];
#pragma unroll
    for (int mf = 0; mf < 4; ++mf)
#pragma unroll
        for (int nf = 0; nf < 4; ++nf)
#pragma unroll
            for (int k = 0; k < 4; ++k) c[mf][nf][k] = 0.f;

#pragma unroll
    for (int pc = 0; pc < 2; ++pc) {      // prologue: stages 0,1
        uint32_t sbase = sb + (uint32_t)(pc * STWB);
        int kb = pc * GKH;
#pragma unroll
        for (int i = 0; i < 2; ++i) {
            asm volatile("cp.async.cg.shared.global [%0], [%1], 16;"
                         :: "r"(sbase + adst[i]), "l"(asrc[i] + kb) : "memory");
            asm volatile("cp.async.cg.shared.global [%0], [%1], 16;"
                         :: "r"(sbase + bdst[i]), "l"(bsrc[i] + kb) : "memory");
        }
        asm volatile("cp.async.commit_group;" ::: "memory");
    }

#pragma unroll 1
    for (int ch = 0; ch < NCHH; ++ch) {
        asm volatile("cp.async.wait_group 1;" ::: "memory");
        __syncthreads();

        {   // issue chunk ch+2 into stage (ch+2)%3
            int nc = ch + 2;
            if (nc < NCHH) {
                uint32_t sbase = sb + (uint32_t)((nc % 3) * STWB);
                int kb = nc * GKH;
#pragma unroll
                for (int i = 0; i < 2; ++i) {
                    asm volatile("cp.async.cg.shared.global [%0], [%1], 16;"
                                 :: "r"(sbase + adst[i]), "l"(asrc[i] + kb)
                                 : "memory");
                    asm volatile("cp.async.cg.shared.global [%0], [%1], 16;"
                                 :: "r"(sbase + bdst[i]), "l"(bsrc[i] + kb)
                                 : "memory");
                }
            }
            asm volatile("cp.async.commit_group;" ::: "memory");
        }

        const uint32_t sbase = sb + (uint32_t)((ch % 3) * STWB);
#pragma unroll
        for (int kk = 0; kk < 2; ++kk) {       // two k16 slices per chunk
            uint32_t a[4][4];
#pragma unroll
            for (int mf = 0; mf < 4; ++mf) {
                int r0 = wm * 64 + mf * 16 + g;
                uint32_t ad0 = sbase + (uint32_t)(r0 * RSB + kk * 32 + tg * 8);
                uint32_t ad1 = sbase +
                    (uint32_t)((r0 + 8) * RSB + kk * 32 + tg * 8);
                // row g    -> (a0 = k-lo pair, a2 = k-hi pair)
                asm volatile("ld.shared.v2.b32 {%0,%1}, [%2];"
                             : "=r"(a[mf][0]), "=r"(a[mf][2]) : "r"(ad0));
                // row g+8  -> (a1, a3)
                asm volatile("ld.shared.v2.b32 {%0,%1}, [%2];"
                             : "=r"(a[mf][1]), "=r"(a[mf][3]) : "r"(ad1));
            }
#pragma unroll
            for (int nf = 0; nf < 4; ++nf) {
                int rn = wn * 32 + nf * 8 + g;
                uint32_t bd = sbase +
                    (uint32_t)(AWB + rn * RSB + kk * 32 + tg * 8);
                uint32_t b0, b1;
                asm volatile("ld.shared.v2.b32 {%0,%1}, [%2];"
                             : "=r"(b0), "=r"(b1) : "r"(bd));
#pragma unroll
                for (int mf = 0; mf < 4; ++mf)
                    mma16h(c[mf][nf], a[mf][0], a[mf][1], a[mf][2], a[mf][3],
                           b0, b1);
            }
        }
    }

    // epilogue: rows -> (s,b) remap, add bias
#pragma unroll
    for (int mf = 0; mf < 4; ++mf) {
        int row = m0 + wm * 64 + mf * 16 + g;
        int s0 = row >> 5, b0i = row & 31;
        int r1 = row + 8;
        int s1 = r1 >> 5, b1i = r1 & 31;
        float* o0 = out + ((size_t)b0i * SEQ + s0) * VOC;
        float* o1 = out + ((size_t)b1i * SEQ + s1) * VOC;
#pragma unroll
        for (int nf = 0; nf < 4; ++nf) {
            int col = n0 + wn * 32 + nf * 8 + 2 * tg;
            float bv0 = bias[col], bv1 = bias[col + 1];
            *(float2*)(o0 + col) = make_float2(c[mf][nf][0] + bv0,
                                               c[mf][nf][1] + bv1);
            *(float2*)(o1 + col) = make_float2(c[mf][nf][2] + bv0,
                                               c[mf][nf][3] + bv1);
        }
    }
}

// ---------------- persistent GRU scan: 128 CTAs (PDL primary) ------------
__global__ void recur_kernel(const float* __restrict__ W_hh,
                             const float* __restrict__ b_hh) {
    // allow the dependent logits GEMM to start launching now
    asm volatile("griddepcontrol.launch_dependents;" ::: "memory");

    extern __shared__ float sm[];
    float* h_sm    = sm;                  // 16384 floats
    float* w_sm    = sm + BSZ * HID;      // 12*512 floats
    float* bias_sm = w_sm + 12 * HID;     // 12 floats

    const int tid = threadIdx.x;
    const int j0  = blockIdx.x * 4;

    for (int i = tid; i < 12 * HID; i += 256) {
        int r = i >> 9, k = i & 511;
        int jl = r / 3, gg = r % 3;
        w_sm[i] = W_hh[(size_t)(gg * HID + j0 + jl) * HID + k];
    }
    if (tid < 12) {
        int jl = tid / 3, gg = tid % 3;
        bias_sm[tid] = b_hh[gg * HID + j0 + jl];
    }

    const int ks = tid & 15;
    const int bq = (tid >> 4) & 3;
    const int jl = tid >> 6;
    const int j  = j0 + jl;
    const float* wr = w_sm + (jl * 3 + 0) * HID;
    const float* wz = w_sm + (jl * 3 + 1) * HID;
    const float* wn = w_sm + (jl * 3 + 2) * HID;
    __syncthreads();

    for (int s = 0; s < SEQ; ++s) {
        float xr[8], xz[8], xn[8];
        if (ks == 0) {
#pragma unroll
            for (int bi = 0; bi < 8; ++bi) {
                int b = bq * 8 + bi;
                const float* xg = g_xg + (size_t)(s * BSZ + b) * NGATE;
                xr[bi] = __ldg(xg + j);
                xz[bi] = __ldg(xg + HID + j);
                xn[bi] = __ldg(xg + 2 * HID + j);
            }
        }

        {
            const float4* src = (const float4*)g_h[s & 1];
            float4* dst = (float4*)h_sm;
            for (int i = tid; i < (BSZ * HID) / 4; i += 256) dst[i] = src[i];
        }
        __syncthreads();

        float ar[8], az[8], an[8];
#pragma unroll
        for (int bi = 0; bi < 8; ++bi) { ar[bi] = az[bi] = an[bi] = 0.f; }
#pragma unroll
        for (int i = 0; i < 8; ++i) {
            int k = ks * 4 + i * 64;
            float4 r4 = *(const float4*)(wr + k);
            float4 z4 = *(const float4*)(wz + k);
            float4 n4 = *(const float4*)(wn + k);
#pragma unroll
            for (int bi = 0; bi < 8; ++bi) {
                int b = bq * 8 + bi;
                float4 h4 = *(const float4*)(h_sm + b * HID + k);
                ar[bi] += h4.x * r4.x + h4.y * r4.y + h4.z * r4.z + h4.w * r4.w;
                az[bi] += h4.x * z4.x + h4.y * z4.y + h4.z * z4.z + h4.w * z4.w;
                an[bi] += h4.x * n4.x + h4.y * n4.y + h4.z * n4.z + h4.w * n4.w;
            }
        }
#pragma unroll
        for (int off = 8; off > 0; off >>= 1) {
#pragma unroll
            for (int bi = 0; bi < 8; ++bi) {
                ar[bi] += __shfl_xor_sync(0xffffffffu, ar[bi], off);
                az[bi] += __shfl_xor_sync(0xffffffffu, az[bi], off);
                an[bi] += __shfl_xor_sync(0xffffffffu, an[bi], off);
            }
        }
        if (ks == 0) {
            float br = bias_sm[jl * 3 + 0];
            float bz = bias_sm[jl * 3 + 1];
            float bn = bias_sm[jl * 3 + 2];
#pragma unroll
            for (int bi = 0; bi < 8; ++bi) {
                int b = bq * 8 + bi;
                float rr = fsigm(xr[bi] + ar[bi] + br);
                float zz = fsigm(xz[bi] + az[bi] + bz);
                float nn = ftanh(xn[bi] + rr * (an[bi] + bn));
                float hold = h_sm[b * HID + j];
                float hnew = (1.f - zz) * nn + zz * hold;
                g_h[(s + 1) & 1][b * HID + j] = hnew;
                g_hs_h[(size_t)(s * BSZ + b) * HID + j] = __float2half_rn(hnew);
            }
        }
        if (s == SEQ - 1) break;

        // ---- grid barrier: store-arrive + all-poll-all ----
        __syncthreads();
        const unsigned sv = (unsigned)(s + 1);
        if (tid == 0) {
            asm volatile("st.release.gpu.global.u32 [%0], %1;"
                         :: "l"(&g_arr[blockIdx.x * 32]), "r"(sv) : "memory");
        }
        if (tid < 32) {
            for (;;) {
                unsigned ok = 1;
#pragma unroll
                for (int i = 0; i < 4; ++i) {
                    unsigned v;
                    asm volatile("ld.acquire.gpu.global.u32 %0, [%1];"
                                 : "=r"(v)
                                 : "l"(&g_arr[(tid * 4 + i) * 32])
                                 : "memory");
                    ok &= (v >= sv) ? 1u : 0u;
                }
                if (__all_sync(0xffffffffu, ok)) break;
            }
        }
        __syncthreads();
    }

    // final arrival: publish step 128 (releases last 4 M-tiles to gemm3)
    __syncthreads();
    if (tid == 0) {
        asm volatile("st.release.gpu.global.u32 [%0], %1;"
                     :: "l"(&g_arr[blockIdx.x * 32]), "r"((unsigned)SEQ)
                     : "memory");
    }
}

// ---------------- launch ----------------
extern "C" void kernel_launch(void* const* d_in, const int* in_sizes, int n_in,
                              void* d_out, int out_size) {
    const float* hidden    = (const float*)d_in[0];
    const void*  targets   = (const void*)d_in[1];
    const float* embedding = (const float*)d_in[2];
    const float* W_ih      = (const float*)d_in[3];
    const float* W_hh      = (const float*)d_in[4];
    const float* b_ih      = (const float*)d_in[5];
    const float* b_hh      = (const float*)d_in[6];
    const float* W_out     = (const float*)d_in[7];
    const float* b_out     = (const float*)d_in[8];
    const int*   init_tok  = (const int*)d_in[9];
    float*       out       = (float*)d_out;

    cudaFuncSetAttribute(recur_kernel,
                         cudaFuncAttributeMaxDynamicSharedMemorySize, 92160);
    cudaFuncSetAttribute(gemm3,
                         cudaFuncAttributeMaxDynamicSharedMemorySize, SMEMH);

    init_kernel<<<16, 256>>>(targets, init_tok, hidden);

    // x_gates: [4096 x 1536 x 512], A gathered from embedding
    gemm_xg<<<dim3(NGATE / 128, NTOK / 128), 256>>>(embedding, W_ih, b_ih);

    // pre-round W_out to fp16 (RN)
    conv_w<<<256, 256>>>(W_out);

    // sequential GRU scan (persistent, 128 co-resident CTAs)
    recur_kernel<<<128, 256, 92160>>>(W_hh, b_hh);

    // logits GEMM (fp16), PDL-overlapped with the scan; gated via g_arr
    {
        cudaLaunchConfig_t cfg = {};
        cfg.gridDim  = dim3(VOC / 128, NTOK / 128);
        cfg.blockDim = dim3(256);
        cfg.dynamicSmemBytes = SMEMH;
        cudaLaunchAttribute attr[1];
        attr[0].id = cudaLaunchAttributeProgrammaticStreamSerialization;
        attr[0].val.programmaticStreamSerializationAllowed = 1;
        cfg.attrs = attr;
        cfg.numAttrs = 1;
        cudaLaunchKernelEx(&cfg, gemm3, (const float*)b_out, out);
    }
}

// round 9
// speedup vs baseline: 2.1736x; 1.1527x over previous
#include <cuda_runtime.h>
#include <cuda_fp16.h>
#include <cstdint>
#include <cmath>

#define BSZ   32
#define SEQ   128
#define HID   512
#define NGATE 1536
#define VOC   32000
#define NTOK  4096   /* BSZ*SEQ */

// ---------------- device scratch (no allocations allowed) ----------------
__device__ int      g_tok[NTOK];
__device__ float    g_xg[(size_t)NTOK * NGATE];    // [S][B][3H], b_ih folded in
__device__ __half   g_hs_h[(size_t)NTOK * HID];    // fp16 hidden states
__device__ __half   g_wout_h[(size_t)VOC * HID];   // fp16 W_out
__device__ float    g_h[2][BSZ * HID];             // ping-pong hidden state
__device__ unsigned g_arr[128 * 32];               // per-CTA arrival slots (128B apart)

__device__ __forceinline__ unsigned f2tf(float x) {
    unsigned r;
    asm("cvt.rna.tf32.f32 %0, %1;" : "=r"(r) : "f"(x));
    return r;
}
__device__ __forceinline__ uint32_t s2u(const void* p) {
    uint32_t a;
    asm("{ .reg .u64 t; cvta.to.shared.u64 t, %1; cvt.u32.u64 %0, t; }"
        : "=r"(a) : "l"(p));
    return a;
}
// packed fp32x2 FMA: d = a*b + d  (two exact fp32 FMAs in one instruction)
__device__ __forceinline__ void fma2(unsigned long long& d,
                                     unsigned long long a,
                                     unsigned long long b) {
    asm("fma.rn.f32x2 %0, %1, %2, %0;" : "+l"(d) : "l"(a), "l"(b));
}
__device__ __forceinline__ float pairsum(unsigned long long v) {
    unsigned lo, hi;
    asm("mov.b64 {%0, %1}, %2;" : "=r"(lo), "=r"(hi) : "l"(v));
    return __uint_as_float(lo) + __uint_as_float(hi);
}

// targets may be int32 (JAX x64 disabled) or int64. Detect: int64 tokens
// always have zero high words -> first 8 int64 views all in [0, VOC).
__device__ __forceinline__ bool tok_is64(const void* p) {
    const long long* q = (const long long*)p;
    bool ok = true;
#pragma unroll
    for (int i = 0; i < 8; ++i) {
        long long v = q[i];
        ok = ok && (v >= 0) && (v < VOC);
    }
    return ok;
}
__device__ __forceinline__ int tok_at(const void* p, int idx, bool is64) {
    return is64 ? (int)((const long long*)p)[idx] : ((const int*)p)[idx];
}

__device__ __forceinline__ float fsigm(float x) {
    return __fdividef(1.f, 1.f + __expf(-x));
}
__device__ __forceinline__ float ftanh(float x) {
    float ax = fabsf(x);
    float e  = __expf(-2.f * ax);
    float t  = __fdividef(1.f - e, 1.f + e);
    return copysignf(t, x);
}

__device__ __forceinline__ void mma8(float* c, const uint32_t* a,
                                     uint32_t b0, uint32_t b1) {
    asm volatile(
        "mma.sync.aligned.m16n8k8.row.col.f32.tf32.tf32.f32 "
        "{%0,%1,%2,%3}, {%4,%5,%6,%7}, {%8,%9}, {%0,%1,%2,%3};"
        : "+f"(c[0]), "+f"(c[1]), "+f"(c[2]), "+f"(c[3])
        : "r"(a[0]), "r"(a[1]), "r"(a[2]), "r"(a[3]), "r"(b0), "r"(b1));
}
__device__ __forceinline__ void mma16h(float* c, uint32_t a0, uint32_t a1,
                                       uint32_t a2, uint32_t a3,
                                       uint32_t b0, uint32_t b1) {
    asm volatile(
        "mma.sync.aligned.m16n8k16.row.col.f32.f16.f16.f32 "
        "{%0,%1,%2,%3}, {%4,%5,%6,%7}, {%8,%9}, {%0,%1,%2,%3};"
        : "+f"(c[0]), "+f"(c[1]), "+f"(c[2]), "+f"(c[3])
        : "r"(a0), "r"(a1), "r"(a2), "r"(a3), "r"(b0), "r"(b1));
}

// ---------------- init: token indices, h0, barrier reset -----------------
__global__ void init_kernel(const void* __restrict__ targets,
                            const int* __restrict__ init_tok,
                            const float* __restrict__ hidden) {
    const bool is64 = tok_is64(targets);
    int t = blockIdx.x * blockDim.x + threadIdx.x;
    int nt = gridDim.x * blockDim.x;
    for (int i = t; i < 128 * 32; i += nt) g_arr[i] = 0u;
    if (t < NTOK) {
        int s = t >> 5, b = t & 31;
        g_tok[t] = (s == 0) ? init_tok[0]
                            : tok_at(targets, b * SEQ + (s - 1), is64);
    }
    for (int i = t; i < BSZ * HID; i += nt)
        g_h[0][i] = hidden[i];
}

// ---------------- pre-convert W_out to fp16 (RN) -------------------------
__global__ void conv_w(const float* __restrict__ W) {
    int t = blockIdx.x * blockDim.x + threadIdx.x;
    int nt = gridDim.x * blockDim.x;
    const int n4 = (VOC * HID) / 4;
    for (int i = t; i < n4; i += nt) {
        float4 v = ((const float4*)W)[i];
        __half2 h01 = __floats2half2_rn(v.x, v.y);
        __half2 h23 = __floats2half2_rn(v.z, v.w);
        *(__half2*)(g_wout_h + (size_t)i * 4)     = h01;
        *(__half2*)(g_wout_h + (size_t)i * 4 + 2) = h23;
    }
}

// ---------------- x_gates GEMM (embedding gather, tf32 mma.sync) ---------
__global__ void __launch_bounds__(256, 2)
gemm_xg(const float* __restrict__ A, const float* __restrict__ Bm,
        const float* __restrict__ bias) {
    __shared__ unsigned As[128 * 36];
    __shared__ unsigned Bs[128 * 36];

    const int tid  = threadIdx.x;
    const int n0   = blockIdx.x * 128;
    const int m0   = blockIdx.y * 128;
    const int lane = tid & 31, warp = tid >> 5;
    const int wm = warp & 1, wn = warp >> 1;
    const int g  = lane >> 2, tg = lane & 3;

    const float* aptr[4];
    const float* bptr[4];
    int soff[4];
#pragma unroll
    for (int i = 0; i < 4; ++i) {
        int idx = tid + i * 256;
        int row = idx >> 3, cv = idx & 7;
        int arow = g_tok[m0 + row];
        aptr[i] = A + (size_t)arow * HID + cv * 4;
        bptr[i] = Bm + (size_t)(n0 + row) * HID + cv * 4;
        soff[i] = row * 36 + cv * 4;
    }

    float c[4][4][4];
#pragma unroll
    for (int a = 0; a < 4; ++a)
#pragma unroll
        for (int b = 0; b < 4; ++b)
#pragma unroll
            for (int k = 0; k < 4; ++k) c[a][b][k] = 0.f;

    for (int kt = 0; kt < 16; ++kt) {
        float4 va[4], vb[4];
#pragma unroll
        for (int i = 0; i < 4; ++i) {
            va[i] = *(const float4*)(aptr[i] + kt * 32);
            vb[i] = *(const float4*)(bptr[i] + kt * 32);
        }
        __syncthreads();
#pragma unroll
        for (int i = 0; i < 4; ++i) {
            As[soff[i] + 0] = f2tf(va[i].x); As[soff[i] + 1] = f2tf(va[i].y);
            As[soff[i] + 2] = f2tf(va[i].z); As[soff[i] + 3] = f2tf(va[i].w);
            Bs[soff[i] + 0] = f2tf(vb[i].x); Bs[soff[i] + 1] = f2tf(vb[i].y);
            Bs[soff[i] + 2] = f2tf(vb[i].z); Bs[soff[i] + 3] = f2tf(vb[i].w);
        }
        __syncthreads();

#pragma unroll
        for (int kk = 0; kk < 4; ++kk) {
            const int kb = kk * 8;
            unsigned afr[4][4], bfr[4][2];
#pragma unroll
            for (int mf = 0; mf < 4; ++mf) {
                int r0 = (wm * 64 + mf * 16 + g) * 36 + kb + tg;
                afr[mf][0] = As[r0];
                afr[mf][1] = As[r0 + 8 * 36];
                afr[mf][2] = As[r0 + 4];
                afr[mf][3] = As[r0 + 8 * 36 + 4];
            }
#pragma unroll
            for (int nf = 0; nf < 4; ++nf) {
                int r0 = (wn * 32 + nf * 8 + g) * 36 + kb + tg;
                bfr[nf][0] = Bs[r0];
                bfr[nf][1] = Bs[r0 + 4];
            }
#pragma unroll
            for (int mf = 0; mf < 4; ++mf)
#pragma unroll
                for (int nf = 0; nf < 4; ++nf)
                    mma8(c[mf][nf], afr[mf], bfr[nf][0], bfr[nf][1]);
        }
    }

#pragma unroll
    for (int mf = 0; mf < 4; ++mf) {
#pragma unroll
        for (int nf = 0; nf < 4; ++nf) {
            int row = m0 + wm * 64 + mf * 16 + g;
            int col = n0 + wn * 32 + nf * 8 + 2 * tg;
            float b0v = bias[col], b1v = bias[col + 1];
            float2 v0 = make_float2(c[mf][nf][0] + b0v, c[mf][nf][1] + b1v);
            float2 v1 = make_float2(c[mf][nf][2] + b0v, c[mf][nf][3] + b1v);
            *(float2*)&g_xg[(size_t)row * NGATE + col]       = v0;
            *(float2*)&g_xg[(size_t)(row + 8) * NGATE + col] = v1;
        }
    }
}

// ---------------- logits GEMM: fp16 m16n8k16, cp.async 3-stage, PDL ------
#define GKH   32            /* halves per chunk */
#define NCHH  16            /* 512 / 32 */
#define RSB   96            /* bytes per row in smem */
#define AWB   (128 * RSB)   /* 12288 B per A stage */
#define STWB  (2 * AWB)     /* 24576 B per stage */
#define SMEMH (3 * STWB)    /* 73728 B */

__global__ void __launch_bounds__(256, 2)
gemm3(const float* __restrict__ bias, float* __restrict__ out) {
    // ---- PDL gate: wait until the scan has produced this tile's rows ----
    {
        const unsigned need = (unsigned)(blockIdx.y * 4 + 4);
        if (threadIdx.x < 32) {
            for (;;) {
                unsigned ok = 1;
#pragma unroll
                for (int i = 0; i < 4; ++i) {
                    unsigned v;
                    asm volatile("ld.acquire.gpu.global.u32 %0, [%1];"
                                 : "=r"(v)
                                 : "l"(&g_arr[(threadIdx.x * 4 + i) * 32])
                                 : "memory");
                    ok &= (v >= need) ? 1u : 0u;
                }
                if (__all_sync(0xffffffffu, ok)) break;
                __nanosleep(256);
            }
        }
        __syncthreads();
    }

    extern __shared__ char smemc[];
    const uint32_t sb = s2u(smemc);
    const int tid  = threadIdx.x;
    const int wid  = tid >> 5, lane = tid & 31;
    const int wm = wid & 1, wn = wid >> 1;         // 2 x 4 warps
    const int g  = lane >> 2, tg = lane & 3;
    const int n0 = blockIdx.x * 128, m0 = blockIdx.y * 128;

    const __half* asrc[2]; uint32_t adst[2];
    const __half* bsrc[2]; uint32_t bdst[2];
#pragma unroll
    for (int i = 0; i < 2; ++i) {
        int idx = tid + i * 256, r = idx >> 2, c4 = idx & 3;
        asrc[i] = g_hs_h + (size_t)(m0 + r) * HID + c4 * 8;
        adst[i] = (uint32_t)(r * RSB + c4 * 16);
        bsrc[i] = g_wout_h + (size_t)(n0 + r) * HID + c4 * 8;
        bdst[i] = (uint32_t)(AWB + r * RSB + c4 * 16);
    }

    float c[4][4][4];
#pragma unroll
    for (int mf = 0; mf < 4; ++mf)
#pragma unroll
        for (int nf = 0; nf < 4; ++nf)
#pragma unroll
            for (int k = 0; k < 4; ++k) c[mf][nf][k] = 0.f;

#pragma unroll
    for (int pc = 0; pc < 2; ++pc) {      // prologue: stages 0,1
        uint32_t sbase = sb + (uint32_t)(pc * STWB);
        int kb = pc * GKH;
#pragma unroll
        for (int i = 0; i < 2; ++i) {
            asm volatile("cp.async.cg.shared.global [%0], [%1], 16;"
                         :: "r"(sbase + adst[i]), "l"(asrc[i] + kb) : "memory");
            asm volatile("cp.async.cg.shared.global [%0], [%1], 16;"
                         :: "r"(sbase + bdst[i]), "l"(bsrc[i] + kb) : "memory");
        }
        asm volatile("cp.async.commit_group;" ::: "memory");
    }

#pragma unroll 1
    for (int ch = 0; ch < NCHH; ++ch) {
        asm volatile("cp.async.wait_group 1;" ::: "memory");
        __syncthreads();

        {   // issue chunk ch+2 into stage (ch+2)%3
            int nc = ch + 2;
            if (nc < NCHH) {
                uint32_t sbase = sb + (uint32_t)((nc % 3) * STWB);
                int kb = nc * GKH;
#pragma unroll
                for (int i = 0; i < 2; ++i) {
                    asm volatile("cp.async.cg.shared.global [%0], [%1], 16;"
                                 :: "r"(sbase + adst[i]), "l"(asrc[i] + kb)
                                 : "memory");
                    asm volatile("cp.async.cg.shared.global [%0], [%1], 16;"
                                 :: "r"(sbase + bdst[i]), "l"(bsrc[i] + kb)
                                 : "memory");
                }
            }
            asm volatile("cp.async.commit_group;" ::: "memory");
        }

        const uint32_t sbase = sb + (uint32_t)((ch % 3) * STWB);
#pragma unroll
        for (int kk = 0; kk < 2; ++kk) {       // two k16 slices per chunk
            uint32_t a[4][4];
#pragma unroll
            for (int mf = 0; mf < 4; ++mf) {
                int r0 = wm * 64 + mf * 16 + g;
                uint32_t ad0 = sbase + (uint32_t)(r0 * RSB + kk * 32 + tg * 8);
                uint32_t ad1 = sbase +
                    (uint32_t)((r0 + 8) * RSB + kk * 32 + tg * 8);
                asm volatile("ld.shared.v2.b32 {%0,%1}, [%2];"
                             : "=r"(a[mf][0]), "=r"(a[mf][2]) : "r"(ad0));
                asm volatile("ld.shared.v2.b32 {%0,%1}, [%2];"
                             : "=r"(a[mf][1]), "=r"(a[mf][3]) : "r"(ad1));
            }
#pragma unroll
            for (int nf = 0; nf < 4; ++nf) {
                int rn = wn * 32 + nf * 8 + g;
                uint32_t bd = sbase +
                    (uint32_t)(AWB + rn * RSB + kk * 32 + tg * 8);
                uint32_t b0, b1;
                asm volatile("ld.shared.v2.b32 {%0,%1}, [%2];"
                             : "=r"(b0), "=r"(b1) : "r"(bd));
#pragma unroll
                for (int mf = 0; mf < 4; ++mf)
                    mma16h(c[mf][nf], a[mf][0], a[mf][1], a[mf][2], a[mf][3],
                           b0, b1);
            }
        }
    }

    // epilogue: rows -> (s,b) remap, add bias
#pragma unroll
    for (int mf = 0; mf < 4; ++mf) {
        int row = m0 + wm * 64 + mf * 16 + g;
        int s0 = row >> 5, b0i = row & 31;
        int r1 = row + 8;
        int s1 = r1 >> 5, b1i = r1 & 31;
        float* o0 = out + ((size_t)b0i * SEQ + s0) * VOC;
        float* o1 = out + ((size_t)b1i * SEQ + s1) * VOC;
#pragma unroll
        for (int nf = 0; nf < 4; ++nf) {
            int col = n0 + wn * 32 + nf * 8 + 2 * tg;
            float bv0 = bias[col], bv1 = bias[col + 1];
            *(float2*)(o0 + col) = make_float2(c[mf][nf][0] + bv0,
                                               c[mf][nf][1] + bv1);
            *(float2*)(o1 + col) = make_float2(c[mf][nf][2] + bv0,
                                               c[mf][nf][3] + bv1);
        }
    }
}

// ---------------- persistent GRU scan: 128 CTAs (PDL primary) ------------
// f32x2 packed FMA (exact fp32), cp.async h broadcast + xg staging.
// smem layout (floats): h 16384 | w 6144 | bias 16 | xg 384
#define RS_H   0
#define RS_W   16384
#define RS_BI  (RS_W + 12 * HID)
#define RS_XG  (RS_BI + 16)
#define RS_TOT ((RS_XG + 384) * 4)     /* 91712 B */

__global__ void __launch_bounds__(256, 2)
recur_kernel(const float* __restrict__ W_hh, const float* __restrict__ b_hh) {
    // allow the dependent logits GEMM to start launching now
    asm volatile("griddepcontrol.launch_dependents;" ::: "memory");

    extern __shared__ float sm[];
    float* h_sm    = sm + RS_H;
    float* w_sm    = sm + RS_W;
    float* bias_sm = sm + RS_BI;
    float* xg_sm   = sm + RS_XG;
    const uint32_t sb = s2u(sm);

    const int tid = threadIdx.x;
    const int j0  = blockIdx.x * 4;

    for (int i = tid; i < 12 * HID; i += 256) {
        int r = i >> 9, k = i & 511;
        int jl = r / 3, gg = r % 3;
        w_sm[i] = W_hh[(size_t)(gg * HID + j0 + jl) * HID + k];
    }
    if (tid < 12) {
        int jl = tid / 3, gg = tid % 3;
        bias_sm[tid] = b_hh[gg * HID + j0 + jl];
    }

    const int ks = tid & 15;
    const int bq = (tid >> 4) & 3;
    const int jl = tid >> 6;
    const int j  = j0 + jl;
    const float* wr = w_sm + (jl * 3 + 0) * HID;
    const float* wz = w_sm + (jl * 3 + 1) * HID;
    const float* wn = w_sm + (jl * 3 + 2) * HID;

    // xg staging slots (tid < 96): b = tid/3, gate chunk g3 = tid%3
    const int xb = tid / 3, xg3 = tid - xb * 3;
    const uint32_t xg_dst = sb + (uint32_t)((RS_XG + xb * 12 + xg3 * 4) * 4);
    const float* xg_srcb = g_xg + (size_t)xb * NGATE + xg3 * HID + j0;

    __syncthreads();

    for (int s = 0; s < SEQ; ++s) {
        // stage xg[s] slice (independent of h; lands in parallel with h)
        if (tid < 96) {
            const float* src = xg_srcb + (size_t)s * BSZ * NGATE;
            asm volatile("cp.async.cg.shared.global [%0], [%1], 16;"
                         :: "r"(xg_dst), "l"(src) : "memory");
        }
        // broadcast h into smem via cp.async (L2-direct, no reg roundtrip)
        {
            const float* src = g_h[s & 1];
#pragma unroll
            for (int t = 0; t < 16; ++t) {
                int idx = tid + t * 256;
                asm volatile("cp.async.cg.shared.global [%0], [%1], 16;"
                             :: "r"(sb + (uint32_t)((RS_H + idx * 4) * 4)),
                                "l"(src + idx * 4) : "memory");
            }
        }
        asm volatile("cp.async.commit_group;" ::: "memory");
        asm volatile("cp.async.wait_group 0;" ::: "memory");
        __syncthreads();

        unsigned long long ar2[8], az2[8], an2[8];
#pragma unroll
        for (int bi = 0; bi < 8; ++bi) { ar2[bi] = az2[bi] = an2[bi] = 0ull; }
#pragma unroll
        for (int i = 0; i < 8; ++i) {
            int k = ks * 4 + i * 64;           // conflict-free per phase group
            ulonglong2 r2 = *(const ulonglong2*)(wr + k);
            ulonglong2 z2 = *(const ulonglong2*)(wz + k);
            ulonglong2 n2 = *(const ulonglong2*)(wn + k);
#pragma unroll
            for (int bi = 0; bi < 8; ++bi) {
                int b = bq * 8 + bi;
                ulonglong2 h2 = *(const ulonglong2*)(h_sm + b * HID + k);
                fma2(ar2[bi], h2.x, r2.x); fma2(ar2[bi], h2.y, r2.y);
                fma2(az2[bi], h2.x, z2.x); fma2(az2[bi], h2.y, z2.y);
                fma2(an2[bi], h2.x, n2.x); fma2(an2[bi], h2.y, n2.y);
            }
        }
        float ar[8], az[8], an[8];
#pragma unroll
        for (int bi = 0; bi < 8; ++bi) {
            ar[bi] = pairsum(ar2[bi]);
            az[bi] = pairsum(az2[bi]);
            an[bi] = pairsum(an2[bi]);
        }
        // reduce across the 16 k-split lanes
#pragma unroll
        for (int off = 8; off > 0; off >>= 1) {
#pragma unroll
            for (int bi = 0; bi < 8; ++bi) {
                ar[bi] += __shfl_xor_sync(0xffffffffu, ar[bi], off);
                az[bi] += __shfl_xor_sync(0xffffffffu, az[bi], off);
                an[bi] += __shfl_xor_sync(0xffffffffu, an[bi], off);
            }
        }
        if (ks == 0) {
            float br = bias_sm[jl * 3 + 0];
            float bz = bias_sm[jl * 3 + 1];
            float bn = bias_sm[jl * 3 + 2];
#pragma unroll
            for (int bi = 0; bi < 8; ++bi) {
                int b = bq * 8 + bi;
                float rr = fsigm(xg_sm[b * 12 + 0 + jl] + ar[bi] + br);
                float zz = fsigm(xg_sm[b * 12 + 4 + jl] + az[bi] + bz);
                float nn = ftanh(xg_sm[b * 12 + 8 + jl] + rr * (an[bi] + bn));
                float hold = h_sm[b * HID + j];
                float hnew = (1.f - zz) * nn + zz * hold;
                g_h[(s + 1) & 1][b * HID + j] = hnew;
                g_hs_h[(size_t)(s * BSZ + b) * HID + j] = __float2half_rn(hnew);
            }
        }
        if (s == SEQ - 1) break;

        // ---- grid barrier: store-arrive + all-poll-all ----
        __syncthreads();
        const unsigned sv = (unsigned)(s + 1);
        if (tid == 0) {
            asm volatile("st.release.gpu.global.u32 [%0], %1;"
                         :: "l"(&g_arr[blockIdx.x * 32]), "r"(sv) : "memory");
        }
        if (tid < 32) {
            for (;;) {
                unsigned ok = 1;
#pragma unroll
                for (int i = 0; i < 4; ++i) {
                    unsigned v;
                    asm volatile("ld.acquire.gpu.global.u32 %0, [%1];"
                                 : "=r"(v)
                                 : "l"(&g_arr[(tid * 4 + i) * 32])
                                 : "memory");
                    ok &= (v >= sv) ? 1u : 0u;
                }
                if (__all_sync(0xffffffffu, ok)) break;
            }
        }
        __syncthreads();
    }

    // final arrival: publish step 128 (releases last 4 M-tiles to gemm3)
    __syncthreads();
    if (tid == 0) {
        asm volatile("st.release.gpu.global.u32 [%0], %1;"
                     :: "l"(&g_arr[blockIdx.x * 32]), "r"((unsigned)SEQ)
                     : "memory");
    }
}

// ---------------- launch ----------------
extern "C" void kernel_launch(void* const* d_in, const int* in_sizes, int n_in,
                              void* d_out, int out_size) {
    const float* hidden    = (const float*)d_in[0];
    const void*  targets   = (const void*)d_in[1];
    const float* embedding = (const float*)d_in[2];
    const float* W_ih      = (const float*)d_in[3];
    const float* W_hh      = (const float*)d_in[4];
    const float* b_ih      = (const float*)d_in[5];
    const float* b_hh      = (const float*)d_in[6];
    const float* W_out     = (const float*)d_in[7];
    const float* b_out     = (const float*)d_in[8];
    const int*   init_tok  = (const int*)d_in[9];
    float*       out       = (float*)d_out;

    cudaFuncSetAttribute(recur_kernel,
                         cudaFuncAttributeMaxDynamicSharedMemorySize, RS_TOT);
    cudaFuncSetAttribute(gemm3,
                         cudaFuncAttributeMaxDynamicSharedMemorySize, SMEMH);

    init_kernel<<<16, 256>>>(targets, init_tok, hidden);

    // x_gates: [4096 x 1536 x 512], A gathered from embedding
    gemm_xg<<<dim3(NGATE / 128, NTOK / 128), 256>>>(embedding, W_ih, b_ih);

    // pre-round W_out to fp16 (RN)
    conv_w<<<256, 256>>>(W_out);

    // sequential GRU scan (persistent, 128 co-resident CTAs)
    recur_kernel<<<128, 256, RS_TOT>>>(W_hh, b_hh);

    // logits GEMM (fp16), PDL-overlapped with the scan; gated via g_arr
    {
        cudaLaunchConfig_t cfg = {};
        cfg.gridDim  = dim3(VOC / 128, NTOK / 128);
        cfg.blockDim = dim3(256);
        cfg.dynamicSmemBytes = SMEMH;
        cudaLaunchAttribute attr[1];
        attr[0].id = cudaLaunchAttributeProgrammaticStreamSerialization;
        attr[0].val.programmaticStreamSerializationAllowed = 1;
        cfg.attrs = attr;
        cfg.numAttrs = 1;
        cudaLaunchKernelEx(&cfg, gemm3, (const float*)b_out, out);
    }
}

// round 10
// speedup vs baseline: 2.3753x; 1.0928x over previous
#include <cuda_runtime.h>
#include <cuda_fp16.h>
#include <cstdint>
#include <cmath>

#define BSZ   32
#define SEQ   128
#define HID   512
#define NGATE 1536
#define VOC   32000
#define NTOK  4096   /* BSZ*SEQ */

// ---------------- device scratch (no allocations allowed) ----------------
__device__ int      g_tok[NTOK];
__device__ float    g_xg[(size_t)NTOK * NGATE];    // [S][B][3H], b_ih folded in
__device__ __half   g_hs_h[(size_t)NTOK * HID];    // fp16 hidden states
__device__ __half   g_wout_h[(size_t)VOC * HID];   // fp16 W_out
__device__ float    g_h[2][BSZ * HID];             // ping-pong hidden state
__device__ unsigned g_arr[128 * 32];               // per-CTA arrival slots (128B apart)

__device__ __forceinline__ unsigned f2tf(float x) {
    unsigned r;
    asm("cvt.rna.tf32.f32 %0, %1;" : "=r"(r) : "f"(x));
    return r;
}
__device__ __forceinline__ uint32_t s2u(const void* p) {
    uint32_t a;
    asm("{ .reg .u64 t; cvta.to.shared.u64 t, %1; cvt.u32.u64 %0, t; }"
        : "=r"(a) : "l"(p));
    return a;
}
// packed fp32x2 FMA: d = a*b + d  (two exact fp32 FMAs in one instruction)
__device__ __forceinline__ void fma2(unsigned long long& d,
                                     unsigned long long a,
                                     unsigned long long b) {
    asm("fma.rn.f32x2 %0, %1, %2, %0;" : "+l"(d) : "l"(a), "l"(b));
}
__device__ __forceinline__ float pairsum(unsigned long long v) {
    unsigned lo, hi;
    asm("mov.b64 {%0, %1}, %2;" : "=r"(lo), "=r"(hi) : "l"(v));
    return __uint_as_float(lo) + __uint_as_float(hi);
}

// targets may be int32 (JAX x64 disabled) or int64. Detect: int64 tokens
// always have zero high words -> first 8 int64 views all in [0, VOC).
__device__ __forceinline__ bool tok_is64(const void* p) {
    const long long* q = (const long long*)p;
    bool ok = true;
#pragma unroll
    for (int i = 0; i < 8; ++i) {
        long long v = q[i];
        ok = ok && (v >= 0) && (v < VOC);
    }
    return ok;
}
__device__ __forceinline__ int tok_at(const void* p, int idx, bool is64) {
    return is64 ? (int)((const long long*)p)[idx] : ((const int*)p)[idx];
}

__device__ __forceinline__ float fsigm(float x) {
    return __fdividef(1.f, 1.f + __expf(-x));
}
__device__ __forceinline__ float ftanh(float x) {
    float ax = fabsf(x);
    float e  = __expf(-2.f * ax);
    float t  = __fdividef(1.f - e, 1.f + e);
    return copysignf(t, x);
}

__device__ __forceinline__ void mma8(float* c, const uint32_t* a,
                                     uint32_t b0, uint32_t b1) {
    asm volatile(
        "mma.sync.aligned.m16n8k8.row.col.f32.tf32.tf32.f32 "
        "{%0,%1,%2,%3}, {%4,%5,%6,%7}, {%8,%9}, {%0,%1,%2,%3};"
        : "+f"(c[0]), "+f"(c[1]), "+f"(c[2]), "+f"(c[3])
        : "r"(a[0]), "r"(a[1]), "r"(a[2]), "r"(a[3]), "r"(b0), "r"(b1));
}
__device__ __forceinline__ void mma16h(float* c, uint32_t a0, uint32_t a1,
                                       uint32_t a2, uint32_t a3,
                                       uint32_t b0, uint32_t b1) {
    asm volatile(
        "mma.sync.aligned.m16n8k16.row.col.f32.f16.f16.f32 "
        "{%0,%1,%2,%3}, {%4,%5,%6,%7}, {%8,%9}, {%0,%1,%2,%3};"
        : "+f"(c[0]), "+f"(c[1]), "+f"(c[2]), "+f"(c[3])
        : "r"(a0), "r"(a1), "r"(a2), "r"(a3), "r"(b0), "r"(b1));
}

// ---------------- init: token indices, h0, barrier reset -----------------
__global__ void init_kernel(const void* __restrict__ targets,
                            const int* __restrict__ init_tok,
                            const float* __restrict__ hidden) {
    const bool is64 = tok_is64(targets);
    int t = blockIdx.x * blockDim.x + threadIdx.x;
    int nt = gridDim.x * blockDim.x;
    for (int i = t; i < 128 * 32; i += nt) g_arr[i] = 0u;
    if (t < NTOK) {
        int s = t >> 5, b = t & 31;
        g_tok[t] = (s == 0) ? init_tok[0]
                            : tok_at(targets, b * SEQ + (s - 1), is64);
    }
    for (int i = t; i < BSZ * HID; i += nt)
        g_h[0][i] = hidden[i];
}

// ---------------- pre-convert W_out to fp16 (RN) -------------------------
__global__ void conv_w(const float* __restrict__ W) {
    int t = blockIdx.x * blockDim.x + threadIdx.x;
    int nt = gridDim.x * blockDim.x;
    const int n4 = (VOC * HID) / 4;
    for (int i = t; i < n4; i += nt) {
        float4 v = ((const float4*)W)[i];
        __half2 h01 = __floats2half2_rn(v.x, v.y);
        __half2 h23 = __floats2half2_rn(v.z, v.w);
        *(__half2*)(g_wout_h + (size_t)i * 4)     = h01;
        *(__half2*)(g_wout_h + (size_t)i * 4 + 2) = h23;
    }
}

// ---------------- x_gates GEMM (embedding gather, tf32 mma.sync) ---------
__global__ void __launch_bounds__(256, 2)
gemm_xg(const float* __restrict__ A, const float* __restrict__ Bm,
        const float* __restrict__ bias) {
    __shared__ unsigned As[128 * 36];
    __shared__ unsigned Bs[128 * 36];

    const int tid  = threadIdx.x;
    const int n0   = blockIdx.x * 128;
    const int m0   = blockIdx.y * 128;
    const int lane = tid & 31, warp = tid >> 5;
    const int wm = warp & 1, wn = warp >> 1;
    const int g  = lane >> 2, tg = lane & 3;

    const float* aptr[4];
    const float* bptr[4];
    int soff[4];
#pragma unroll
    for (int i = 0; i < 4; ++i) {
        int idx = tid + i * 256;
        int row = idx >> 3, cv = idx & 7;
        int arow = g_tok[m0 + row];
        aptr[i] = A + (size_t)arow * HID + cv * 4;
        bptr[i] = Bm + (size_t)(n0 + row) * HID + cv * 4;
        soff[i] = row * 36 + cv * 4;
    }

    float c[4][4][4];
#pragma unroll
    for (int a = 0; a < 4; ++a)
#pragma unroll
        for (int b = 0; b < 4; ++b)
#pragma unroll
            for (int k = 0; k < 4; ++k) c[a][b][k] = 0.f;

    for (int kt = 0; kt < 16; ++kt) {
        float4 va[4], vb[4];
#pragma unroll
        for (int i = 0; i < 4; ++i) {
            va[i] = *(const float4*)(aptr[i] + kt * 32);
            vb[i] = *(const float4*)(bptr[i] + kt * 32);
        }
        __syncthreads();
#pragma unroll
        for (int i = 0; i < 4; ++i) {
            As[soff[i] + 0] = f2tf(va[i].x); As[soff[i] + 1] = f2tf(va[i].y);
            As[soff[i] + 2] = f2tf(va[i].z); As[soff[i] + 3] = f2tf(va[i].w);
            Bs[soff[i] + 0] = f2tf(vb[i].x); Bs[soff[i] + 1] = f2tf(vb[i].y);
            Bs[soff[i] + 2] = f2tf(vb[i].z); Bs[soff[i] + 3] = f2tf(vb[i].w);
        }
        __syncthreads();

#pragma unroll
        for (int kk = 0; kk < 4; ++kk) {
            const int kb = kk * 8;
            unsigned afr[4][4], bfr[4][2];
#pragma unroll
            for (int mf = 0; mf < 4; ++mf) {
                int r0 = (wm * 64 + mf * 16 + g) * 36 + kb + tg;
                afr[mf][0] = As[r0];
                afr[mf][1] = As[r0 + 8 * 36];
                afr[mf][2] = As[r0 + 4];
                afr[mf][3] = As[r0 + 8 * 36 + 4];
            }
#pragma unroll
            for (int nf = 0; nf < 4; ++nf) {
                int r0 = (wn * 32 + nf * 8 + g) * 36 + kb + tg;
                bfr[nf][0] = Bs[r0];
                bfr[nf][1] = Bs[r0 + 4];
            }
#pragma unroll
            for (int mf = 0; mf < 4; ++mf)
#pragma unroll
                for (int nf = 0; nf < 4; ++nf)
                    mma8(c[mf][nf], afr[mf], bfr[nf][0], bfr[nf][1]);
        }
    }

#pragma unroll
    for (int mf = 0; mf < 4; ++mf) {
#pragma unroll
        for (int nf = 0; nf < 4; ++nf) {
            int row = m0 + wm * 64 + mf * 16 + g;
            int col = n0 + wn * 32 + nf * 8 + 2 * tg;
            float b0v = bias[col], b1v = bias[col + 1];
            float2 v0 = make_float2(c[mf][nf][0] + b0v, c[mf][nf][1] + b1v);
            float2 v1 = make_float2(c[mf][nf][2] + b0v, c[mf][nf][3] + b1v);
            *(float2*)&g_xg[(size_t)row * NGATE + col]       = v0;
            *(float2*)&g_xg[(size_t)(row + 8) * NGATE + col] = v1;
        }
    }
}

// ---------------- logits GEMM: fp16 m16n8k16, cp.async 3-stage, PDL ------
#define GKH   32            /* halves per chunk */
#define NCHH  16            /* 512 / 32 */
#define RSB   96            /* bytes per row in smem */
#define AWB   (128 * RSB)   /* 12288 B per A stage */
#define STWB  (2 * AWB)     /* 24576 B per stage */
#define SMEMH (3 * STWB)    /* 73728 B */

__global__ void __launch_bounds__(256, 2)
gemm3(const float* __restrict__ bias, float* __restrict__ out) {
    // ---- PDL gate: wait until the scan has produced this tile's rows ----
    {
        const unsigned need = (unsigned)(blockIdx.y * 4 + 4);
        if (threadIdx.x < 32) {
            for (;;) {
                unsigned ok = 1;
#pragma unroll
                for (int i = 0; i < 4; ++i) {
                    unsigned v;
                    asm volatile("ld.acquire.gpu.global.u32 %0, [%1];"
                                 : "=r"(v)
                                 : "l"(&g_arr[(threadIdx.x * 4 + i) * 32])
                                 : "memory");
                    ok &= (v >= need) ? 1u : 0u;
                }
                if (__all_sync(0xffffffffu, ok)) break;
                __nanosleep(256);
            }
        }
        __syncthreads();
    }

    extern __shared__ char smemc[];
    const uint32_t sb = s2u(smemc);
    const int tid  = threadIdx.x;
    const int wid  = tid >> 5, lane = tid & 31;
    const int wm = wid & 1, wn = wid >> 1;         // 2 x 4 warps
    const int g  = lane >> 2, tg = lane & 3;
    const int n0 = blockIdx.x * 128, m0 = blockIdx.y * 128;

    const __half* asrc[2]; uint32_t adst[2];
    const __half* bsrc[2]; uint32_t bdst[2];
#pragma unroll
    for (int i = 0; i < 2; ++i) {
        int idx = tid + i * 256, r = idx >> 2, c4 = idx & 3;
        asrc[i] = g_hs_h + (size_t)(m0 + r) * HID + c4 * 8;
        adst[i] = (uint32_t)(r * RSB + c4 * 16);
        bsrc[i] = g_wout_h + (size_t)(n0 + r) * HID + c4 * 8;
        bdst[i] = (uint32_t)(AWB + r * RSB + c4 * 16);
    }

    float c[4][4][4];
#pragma unroll
    for (int mf = 0; mf < 4; ++mf)
#pragma unroll
        for (int nf = 0; nf < 4; ++nf)
#pragma unroll
            for (int k = 0; k < 4; ++k) c[mf][nf][k] = 0.f;

#pragma unroll
    for (int pc = 0; pc < 2; ++pc) {      // prologue: stages 0,1
        uint32_t sbase = sb + (uint32_t)(pc * STWB);
        int kb = pc * GKH;
#pragma unroll
        for (int i = 0; i < 2; ++i) {
            asm volatile("cp.async.cg.shared.global [%0], [%1], 16;"
                         :: "r"(sbase + adst[i]), "l"(asrc[i] + kb) : "memory");
            asm volatile("cp.async.cg.shared.global [%0], [%1], 16;"
                         :: "r"(sbase + bdst[i]), "l"(bsrc[i] + kb) : "memory");
        }
        asm volatile("cp.async.commit_group;" ::: "memory");
    }

#pragma unroll 1
    for (int ch = 0; ch < NCHH; ++ch) {
        asm volatile("cp.async.wait_group 1;" ::: "memory");
        __syncthreads();

        {   // issue chunk ch+2 into stage (ch+2)%3
            int nc = ch + 2;
            if (nc < NCHH) {
                uint32_t sbase = sb + (uint32_t)((nc % 3) * STWB);
                int kb = nc * GKH;
#pragma unroll
                for (int i = 0; i < 2; ++i) {
                    asm volatile("cp.async.cg.shared.global [%0], [%1], 16;"
                                 :: "r"(sbase + adst[i]), "l"(asrc[i] + kb)
                                 : "memory");
                    asm volatile("cp.async.cg.shared.global [%0], [%1], 16;"
                                 :: "r"(sbase + bdst[i]), "l"(bsrc[i] + kb)
                                 : "memory");
                }
            }
            asm volatile("cp.async.commit_group;" ::: "memory");
        }

        const uint32_t sbase = sb + (uint32_t)((ch % 3) * STWB);
#pragma unroll
        for (int kk = 0; kk < 2; ++kk) {       // two k16 slices per chunk
            uint32_t a[4][4];
#pragma unroll
            for (int mf = 0; mf < 4; ++mf) {
                int r0 = wm * 64 + mf * 16 + g;
                uint32_t ad0 = sbase + (uint32_t)(r0 * RSB + kk * 32 + tg * 8);
                uint32_t ad1 = sbase +
                    (uint32_t)((r0 + 8) * RSB + kk * 32 + tg * 8);
                asm volatile("ld.shared.v2.b32 {%0,%1}, [%2];"
                             : "=r"(a[mf][0]), "=r"(a[mf][2]) : "r"(ad0));
                asm volatile("ld.shared.v2.b32 {%0,%1}, [%2];"
                             : "=r"(a[mf][1]), "=r"(a[mf][3]) : "r"(ad1));
            }
#pragma unroll
            for (int nf = 0; nf < 4; ++nf) {
                int rn = wn * 32 + nf * 8 + g;
                uint32_t bd = sbase +
                    (uint32_t)(AWB + rn * RSB + kk * 32 + tg * 8);
                uint32_t b0, b1;
                asm volatile("ld.shared.v2.b32 {%0,%1}, [%2];"
                             : "=r"(b0), "=r"(b1) : "r"(bd));
#pragma unroll
                for (int mf = 0; mf < 4; ++mf)
                    mma16h(c[mf][nf], a[mf][0], a[mf][1], a[mf][2], a[mf][3],
                           b0, b1);
            }
        }
    }

    // epilogue: rows -> (s,b) remap, add bias
#pragma unroll
    for (int mf = 0; mf < 4; ++mf) {
        int row = m0 + wm * 64 + mf * 16 + g;
        int s0 = row >> 5, b0i = row & 31;
        int r1 = row + 8;
        int s1 = r1 >> 5, b1i = r1 & 31;
        float* o0 = out + ((size_t)b0i * SEQ + s0) * VOC;
        float* o1 = out + ((size_t)b1i * SEQ + s1) * VOC;
#pragma unroll
        for (int nf = 0; nf < 4; ++nf) {
            int col = n0 + wn * 32 + nf * 8 + 2 * tg;
            float bv0 = bias[col], bv1 = bias[col + 1];
            *(float2*)(o0 + col) = make_float2(c[mf][nf][0] + bv0,
                                               c[mf][nf][1] + bv1);
            *(float2*)(o1 + col) = make_float2(c[mf][nf][2] + bv0,
                                               c[mf][nf][3] + bv1);
        }
    }
}

// ---------------- persistent GRU scan: 64 j-groups x 2 batch-groups ------
// CTA c: jg = c>>1 (8 j's), bg = c&1 (16 batches). Batch columns are
// independent recurrences: barrier scope = 64 CTAs of own column.
// f32x2 packed FMA (exact fp32), cp.async h broadcast (32KB) + xg staging.
// smem (floats): h 8192 | w 12288 (24 rows x 512) | bias 32 | xg 384
#define RS_H   0
#define RS_W   8192
#define RS_BI  (RS_W + 24 * HID)
#define RS_XG  (RS_BI + 32)
#define RS_TOT ((RS_XG + 384) * 4)     /* 83584 B */

__global__ void __launch_bounds__(256, 2)
recur_kernel(const float* __restrict__ W_hh, const float* __restrict__ b_hh) {
    // allow the dependent logits GEMM to start launching now
    asm volatile("griddepcontrol.launch_dependents;" ::: "memory");

    extern __shared__ float sm[];
    float* h_sm    = sm + RS_H;
    float* w_sm    = sm + RS_W;
    float* bias_sm = sm + RS_BI;
    float* xg_sm   = sm + RS_XG;
    const uint32_t sb = s2u(sm);

    const int tid = threadIdx.x;
    const int bg  = blockIdx.x & 1;
    const int jg  = blockIdx.x >> 1;
    const int j0  = jg * 8;
    const int bbase = bg * 16;

    // load W slice: 24 rows (8 local j x 3 gates) x 512
    for (int i = tid; i < 24 * HID; i += 256) {
        int r = i >> 9, k = i & 511;
        int lj = r / 3, gg = r % 3;
        w_sm[i] = W_hh[(size_t)(gg * HID + j0 + lj) * HID + k];
    }
    if (tid < 24) {
        int lj = tid / 3, gg = tid % 3;
        bias_sm[tid] = b_hh[gg * HID + j0 + lj];
    }

    const int ks = tid & 15;          // 16-way k split
    const int bq = (tid >> 4) & 3;    // 4 batches each (local)
    const int jl = tid >> 6;          // 2 local j each: lj = jl*2 + jj
    const float* wp[6];               // [jj*3 + gate]
#pragma unroll
    for (int jj = 0; jj < 2; ++jj)
#pragma unroll
        for (int gg = 0; gg < 3; ++gg)
            wp[jj * 3 + gg] = w_sm + ((jl * 2 + jj) * 3 + gg) * HID;

    // xg staging (tid < 96): b_loc = tid/6, gate = (tid%6)/2, half = tid&1
    const int xbl = tid / 6, xrem = tid - xbl * 6;
    const int xgt = xrem >> 1, xhf = xrem & 1;
    const uint32_t xg_dst =
        sb + (uint32_t)((RS_XG + xbl * 24 + xgt * 8 + xhf * 4) * 4);
    const float* xg_srcb =
        g_xg + (size_t)(bbase + xbl) * NGATE + xgt * HID + j0 + xhf * 4;

    __syncthreads();

    for (int s = 0; s < SEQ; ++s) {
        // stage xg[s] slice (independent of h)
        if (tid < 96) {
            const float* src = xg_srcb + (size_t)s * BSZ * NGATE;
            asm volatile("cp.async.cg.shared.global [%0], [%1], 16;"
                         :: "r"(xg_dst), "l"(src) : "memory");
        }
        // broadcast own batch column's h (16 x 512 = 32KB) into smem
        {
            const float* src = g_h[s & 1] + bbase * HID;
#pragma unroll
            for (int t = 0; t < 8; ++t) {
                int idx = tid + t * 256;
                asm volatile("cp.async.cg.shared.global [%0], [%1], 16;"
                             :: "r"(sb + (uint32_t)((RS_H + idx * 4) * 4)),
                                "l"(src + idx * 4) : "memory");
            }
        }
        asm volatile("cp.async.commit_group;" ::: "memory");
        asm volatile("cp.async.wait_group 0;" ::: "memory");
        __syncthreads();

        unsigned long long acc[6][4];   // [jj*3+gate][bi]
#pragma unroll
        for (int q = 0; q < 6; ++q)
#pragma unroll
            for (int bi = 0; bi < 4; ++bi) acc[q][bi] = 0ull;

#pragma unroll
        for (int i = 0; i < 8; ++i) {
            int k = ks * 4 + i * 64;
            ulonglong2 w2[6];
#pragma unroll
            for (int q = 0; q < 6; ++q)
                w2[q] = *(const ulonglong2*)(wp[q] + k);
#pragma unroll
            for (int bi = 0; bi < 4; ++bi) {
                int bl = bq * 4 + bi;
                ulonglong2 h2 = *(const ulonglong2*)(h_sm + bl * HID + k);
#pragma unroll
                for (int q = 0; q < 6; ++q) {
                    fma2(acc[q][bi], h2.x, w2[q].x);
                    fma2(acc[q][bi], h2.y, w2[q].y);
                }
            }
        }
        float a[6][4];
#pragma unroll
        for (int q = 0; q < 6; ++q)
#pragma unroll
            for (int bi = 0; bi < 4; ++bi) a[q][bi] = pairsum(acc[q][bi]);
        // reduce across the 16 k-split lanes
#pragma unroll
        for (int off = 8; off > 0; off >>= 1) {
#pragma unroll
            for (int q = 0; q < 6; ++q)
#pragma unroll
                for (int bi = 0; bi < 4; ++bi)
                    a[q][bi] += __shfl_xor_sync(0xffffffffu, a[q][bi], off);
        }
        if (ks == 0) {
#pragma unroll
            for (int jj = 0; jj < 2; ++jj) {
                int lj = jl * 2 + jj;
                int j  = j0 + lj;
                float br = bias_sm[lj * 3 + 0];
                float bz = bias_sm[lj * 3 + 1];
                float bn = bias_sm[lj * 3 + 2];
#pragma unroll
                for (int bi = 0; bi < 4; ++bi) {
                    int bl = bq * 4 + bi;
                    int b  = bbase + bl;
                    float rr = fsigm(xg_sm[bl * 24 + 0 + lj] + a[jj * 3 + 0][bi] + br);
                    float zz = fsigm(xg_sm[bl * 24 + 8 + lj] + a[jj * 3 + 1][bi] + bz);
                    float nn = ftanh(xg_sm[bl * 24 + 16 + lj] +
                                     rr * (a[jj * 3 + 2][bi] + bn));
                    float hold = h_sm[bl * HID + j];
                    float hnew = (1.f - zz) * nn + zz * hold;
                    g_h[(s + 1) & 1][b * HID + j] = hnew;
                    g_hs_h[(size_t)(s * BSZ + b) * HID + j] =
                        __float2half_rn(hnew);
                }
            }
        }
        if (s == SEQ - 1) break;

        // ---- column barrier: store-arrive + poll own 64 CTAs ----
        __syncthreads();
        const unsigned sv = (unsigned)(s + 1);
        if (tid == 0) {
            asm volatile("st.release.gpu.global.u32 [%0], %1;"
                         :: "l"(&g_arr[blockIdx.x * 32]), "r"(sv) : "memory");
        }
        if (tid < 32) {
            for (;;) {
                unsigned ok = 1;
#pragma unroll
                for (int i = 0; i < 2; ++i) {
                    int cc = 2 * (tid * 2 + i) + bg;   // same-column CTA ids
                    unsigned v;
                    asm volatile("ld.acquire.gpu.global.u32 %0, [%1];"
                                 : "=r"(v) : "l"(&g_arr[cc * 32])
                                 : "memory");
                    ok &= (v >= sv) ? 1u : 0u;
                }
                if (__all_sync(0xffffffffu, ok)) break;
            }
        }
        __syncthreads();
    }

    // final arrival: publish step 128 (releases last M-tiles to gemm3)
    __syncthreads();
    if (tid == 0) {
        asm volatile("st.release.gpu.global.u32 [%0], %1;"
                     :: "l"(&g_arr[blockIdx.x * 32]), "r"((unsigned)SEQ)
                     : "memory");
    }
}

// ---------------- launch ----------------
extern "C" void kernel_launch(void* const* d_in, const int* in_sizes, int n_in,
                              void* d_out, int out_size) {
    const float* hidden    = (const float*)d_in[0];
    const void*  targets   = (const void*)d_in[1];
    const float* embedding = (const float*)d_in[2];
    const float* W_ih      = (const float*)d_in[3];
    const float* W_hh      = (const float*)d_in[4];
    const float* b_ih      = (const float*)d_in[5];
    const float* b_hh      = (const float*)d_in[6];
    const float* W_out     = (const float*)d_in[7];
    const float* b_out     = (const float*)d_in[8];
    const int*   init_tok  = (const int*)d_in[9];
    float*       out       = (float*)d_out;

    cudaFuncSetAttribute(recur_kernel,
                         cudaFuncAttributeMaxDynamicSharedMemorySize, RS_TOT);
    cudaFuncSetAttribute(gemm3,
                         cudaFuncAttributeMaxDynamicSharedMemorySize, SMEMH);

    init_kernel<<<16, 256>>>(targets, init_tok, hidden);

    // x_gates: [4096 x 1536 x 512], A gathered from embedding
    gemm_xg<<<dim3(NGATE / 128, NTOK / 128), 256>>>(embedding, W_ih, b_ih);

    // pre-round W_out to fp16 (RN)
    conv_w<<<256, 256>>>(W_out);

    // sequential GRU scan (persistent, 128 co-resident CTAs)
    recur_kernel<<<128, 256, RS_TOT>>>(W_hh, b_hh);

    // logits GEMM (fp16), PDL-overlapped with the scan; gated via g_arr
    {
        cudaLaunchConfig_t cfg = {};
        cfg.gridDim  = dim3(VOC / 128, NTOK / 128);
        cfg.blockDim = dim3(256);
        cfg.dynamicSmemBytes = SMEMH;
        cudaLaunchAttribute attr[1];
        attr[0].id = cudaLaunchAttributeProgrammaticStreamSerialization;
        attr[0].val.programmaticStreamSerializationAllowed = 1;
        cfg.attrs = attr;
        cfg.numAttrs = 1;
        cudaLaunchKernelEx(&cfg, gemm3, (const float*)b_out, out);
    }
}